// round 1
// baseline (speedup 1.0000x reference)
#include <cuda_runtime.h>
#include <cstdint>

// Problem constants
#define BB 2
#define TT 2048
#define CC 2048
#define HH 16
#define HD 128
#define M1 (BB*TT)      // 4096
#define N1 (3*CC)       // 6144
#define K1 CC           // 2048

// Scratch (device globals; no allocation allowed)
__device__ float g_q[BB*HH*TT*HD];
__device__ float g_k[BB*HH*TT*HD];
__device__ float g_v[BB*HH*TT*HD];
__device__ float g_y[BB*TT*CC];

// ---------------------------------------------------------------------------
// SGEMM: 128x128 tile, BK=16, 256 threads, 8x8 per-thread register tile.
// C = A(MxK, row-major) * W(NxK, row-major)^T
// ---------------------------------------------------------------------------
#define BM 128
#define BN 128
#define BKG 16
#define APAD 4
#define ASTR (BM + APAD)

// Epilogue: scatter qkv into [B,H,T,HD] q/k/v buffers
__global__ __launch_bounds__(256, 2)
void sgemm_qkv(const float* __restrict__ A, const float* __restrict__ W,
               float* __restrict__ q, float* __restrict__ k, float* __restrict__ v)
{
    const int Kd = K1;
    __shared__ float As[BKG][ASTR];
    __shared__ float Bs[BKG][ASTR];

    const int tid = threadIdx.x;
    const int tx = tid & 15;
    const int ty = tid >> 4;
    const int m0 = blockIdx.y * BM;
    const int n0 = blockIdx.x * BN;

    float acc[8][8];
#pragma unroll
    for (int i = 0; i < 8; i++)
#pragma unroll
        for (int j = 0; j < 8; j++) acc[i][j] = 0.0f;

    for (int kt = 0; kt < Kd; kt += BKG) {
#pragma unroll
        for (int it = 0; it < 2; it++) {
            int idx = tid + it * 256;       // 0..511 float4 slots
            int r   = idx >> 2;             // 0..127
            int c4  = (idx & 3) * 4;        // 0,4,8,12
            float4 av = *(const float4*)&A[(size_t)(m0 + r) * Kd + kt + c4];
            As[c4 + 0][r] = av.x; As[c4 + 1][r] = av.y;
            As[c4 + 2][r] = av.z; As[c4 + 3][r] = av.w;
            float4 bv = *(const float4*)&W[(size_t)(n0 + r) * Kd + kt + c4];
            Bs[c4 + 0][r] = bv.x; Bs[c4 + 1][r] = bv.y;
            Bs[c4 + 2][r] = bv.z; Bs[c4 + 3][r] = bv.w;
        }
        __syncthreads();

#pragma unroll
        for (int kk = 0; kk < BKG; kk++) {
            float a[8], b[8];
            *(float4*)&a[0] = *(float4*)&As[kk][ty * 8];
            *(float4*)&a[4] = *(float4*)&As[kk][ty * 8 + 4];
            *(float4*)&b[0] = *(float4*)&Bs[kk][tx * 8];
            *(float4*)&b[4] = *(float4*)&Bs[kk][tx * 8 + 4];
#pragma unroll
            for (int i = 0; i < 8; i++)
#pragma unroll
                for (int j = 0; j < 8; j++)
                    acc[i][j] += a[i] * b[j];
        }
        __syncthreads();
    }

    // scatter: n = which*2048 + h*128 + d ;  m = b*T + t
#pragma unroll
    for (int i = 0; i < 8; i++) {
        int m  = m0 + ty * 8 + i;
        int bb = m >> 11;           // /2048
        int t  = m & 2047;
#pragma unroll
        for (int j = 0; j < 8; j++) {
            int n     = n0 + tx * 8 + j;
            int which = n >> 11;
            int c     = n & 2047;
            int h     = c >> 7;
            int d     = c & 127;
            float* dst = (which == 0) ? q : ((which == 1) ? k : v);
            dst[(((size_t)(bb * HH + h)) * TT + t) * HD + d] = acc[i][j];
        }
    }
}

// Epilogue: plain row-major store + bias
__global__ __launch_bounds__(256, 2)
void sgemm_proj(const float* __restrict__ A, const float* __restrict__ W,
                const float* __restrict__ bias, float* __restrict__ Cout)
{
    const int Kd = CC, Nd = CC;
    __shared__ float As[BKG][ASTR];
    __shared__ float Bs[BKG][ASTR];

    const int tid = threadIdx.x;
    const int tx = tid & 15;
    const int ty = tid >> 4;
    const int m0 = blockIdx.y * BM;
    const int n0 = blockIdx.x * BN;

    float acc[8][8];
#pragma unroll
    for (int i = 0; i < 8; i++)
#pragma unroll
        for (int j = 0; j < 8; j++) acc[i][j] = 0.0f;

    for (int kt = 0; kt < Kd; kt += BKG) {
#pragma unroll
        for (int it = 0; it < 2; it++) {
            int idx = tid + it * 256;
            int r   = idx >> 2;
            int c4  = (idx & 3) * 4;
            float4 av = *(const float4*)&A[(size_t)(m0 + r) * Kd + kt + c4];
            As[c4 + 0][r] = av.x; As[c4 + 1][r] = av.y;
            As[c4 + 2][r] = av.z; As[c4 + 3][r] = av.w;
            float4 bv = *(const float4*)&W[(size_t)(n0 + r) * Kd + kt + c4];
            Bs[c4 + 0][r] = bv.x; Bs[c4 + 1][r] = bv.y;
            Bs[c4 + 2][r] = bv.z; Bs[c4 + 3][r] = bv.w;
        }
        __syncthreads();

#pragma unroll
        for (int kk = 0; kk < BKG; kk++) {
            float a[8], b[8];
            *(float4*)&a[0] = *(float4*)&As[kk][ty * 8];
            *(float4*)&a[4] = *(float4*)&As[kk][ty * 8 + 4];
            *(float4*)&b[0] = *(float4*)&Bs[kk][tx * 8];
            *(float4*)&b[4] = *(float4*)&Bs[kk][tx * 8 + 4];
#pragma unroll
            for (int i = 0; i < 8; i++)
#pragma unroll
                for (int j = 0; j < 8; j++)
                    acc[i][j] += a[i] * b[j];
        }
        __syncthreads();
    }

#pragma unroll
    for (int i = 0; i < 8; i++) {
        int m = m0 + ty * 8 + i;
#pragma unroll
        for (int j = 0; j < 8; j++) {
            int n = n0 + tx * 8 + j;
            Cout[(size_t)m * Nd + n] = acc[i][j] + bias[n];
        }
    }
}

// ---------------------------------------------------------------------------
// Flash attention (fp32, causal). BQ=64, BKV=64, D=128. 256 threads (16x16).
// Each thread owns 4 query rows x (4 S-cols / 8 O-cols).
// ---------------------------------------------------------------------------
#define BQ 64
#define BKV 64
#define QSTR 132          // 128 + 4 pad
#define PSTR 68           // 64 + 4 pad
#define FLASH_SMEM ((BQ*QSTR*3 + BQ*PSTR) * 4)

__global__ __launch_bounds__(256, 1)
void flash_attn(const float* __restrict__ q, const float* __restrict__ k,
                const float* __restrict__ v, float* __restrict__ y)
{
    extern __shared__ float smem[];
    float* Qs = smem;
    float* Ks = Qs + BQ * QSTR;
    float* Vs = Ks + BQ * QSTR;
    float* Ps = Vs + BQ * QSTR;

    const int qt  = blockIdx.x;   // 0..31 query tile
    const int bh  = blockIdx.y;   // 0..31 (b*H + h)
    const int tid = threadIdx.x;
    const int tx  = tid & 15;
    const int ty  = tid >> 4;
    const float scale = 0.08838834764831845f; // 1/sqrt(128)

    const size_t base = (size_t)bh * TT * HD;

    // Load Q tile: 64x128 floats = 2048 float4, 8 per thread
#pragma unroll
    for (int it = 0; it < 8; it++) {
        int idx = tid + it * 256;
        int r   = idx >> 5;         // 32 float4 per row
        int d4  = (idx & 31) * 4;
        *(float4*)&Qs[r * QSTR + d4] =
            *(const float4*)&q[base + (size_t)(qt * BQ + r) * HD + d4];
    }

    float m_i[4], l_i[4], o[4][8];
#pragma unroll
    for (int i = 0; i < 4; i++) {
        m_i[i] = -1e30f;
        l_i[i] = 0.0f;
#pragma unroll
        for (int j = 0; j < 8; j++) o[i][j] = 0.0f;
    }

    const int nkt = qt + 1;  // causal: only tiles <= qt
    for (int jt = 0; jt < nkt; jt++) {
        __syncthreads();  // previous iter done with Ks/Vs/Ps; Qs ready (first iter)

        // Load K, V tiles
#pragma unroll
        for (int it = 0; it < 8; it++) {
            int idx = tid + it * 256;
            int r   = idx >> 5;
            int d4  = (idx & 31) * 4;
            size_t g = base + (size_t)(jt * BKV + r) * HD + d4;
            *(float4*)&Ks[r * QSTR + d4] = *(const float4*)&k[g];
            *(float4*)&Vs[r * QSTR + d4] = *(const float4*)&v[g];
        }
        __syncthreads();

        // S = Q K^T (4x4 per thread)
        float s[4][4];
#pragma unroll
        for (int i = 0; i < 4; i++)
#pragma unroll
            for (int j = 0; j < 4; j++) s[i][j] = 0.0f;

        for (int d4 = 0; d4 < HD; d4 += 4) {
            float4 qv[4], kv[4];
#pragma unroll
            for (int i = 0; i < 4; i++)
                qv[i] = *(float4*)&Qs[(ty * 4 + i) * QSTR + d4];
#pragma unroll
            for (int j = 0; j < 4; j++)
                kv[j] = *(float4*)&Ks[(tx * 4 + j) * QSTR + d4];
#pragma unroll
            for (int i = 0; i < 4; i++)
#pragma unroll
                for (int j = 0; j < 4; j++) {
                    s[i][j] += qv[i].x * kv[j].x;
                    s[i][j] += qv[i].y * kv[j].y;
                    s[i][j] += qv[i].z * kv[j].z;
                    s[i][j] += qv[i].w * kv[j].w;
                }
        }

        const bool diag = (jt == qt);
#pragma unroll
        for (int i = 0; i < 4; i++) {
            int qg = qt * BQ + ty * 4 + i;
#pragma unroll
            for (int j = 0; j < 4; j++) {
                int kg = jt * BKV + tx * 4 + j;
                s[i][j] *= scale;
                if (diag && kg > qg) s[i][j] = -1e30f;
            }
        }

        // Online softmax per row (reduce over 16 tx lanes; width 16 matches lane%16)
#pragma unroll
        for (int i = 0; i < 4; i++) {
            float mx = fmaxf(fmaxf(s[i][0], s[i][1]), fmaxf(s[i][2], s[i][3]));
#pragma unroll
            for (int off = 8; off >= 1; off >>= 1)
                mx = fmaxf(mx, __shfl_xor_sync(0xffffffffu, mx, off, 16));
            float mnew = fmaxf(m_i[i], mx);
            float corr = __expf(m_i[i] - mnew);
            float rs = 0.0f;
#pragma unroll
            for (int j = 0; j < 4; j++) {
                s[i][j] = __expf(s[i][j] - mnew);
                rs += s[i][j];
            }
#pragma unroll
            for (int off = 8; off >= 1; off >>= 1)
                rs += __shfl_xor_sync(0xffffffffu, rs, off, 16);
            l_i[i] = l_i[i] * corr + rs;
            m_i[i] = mnew;
#pragma unroll
            for (int jc = 0; jc < 8; jc++) o[i][jc] *= corr;
            // publish P
#pragma unroll
            for (int j = 0; j < 4; j++)
                Ps[(ty * 4 + i) * PSTR + tx * 4 + j] = s[i][j];
        }
        __syncthreads();

        // O += P @ V   (each thread: 4 rows x 8 cols, cols = tx*8 .. tx*8+7)
        for (int kk = 0; kk < BKV; kk++) {
            float p[4];
#pragma unroll
            for (int i = 0; i < 4; i++)
                p[i] = Ps[(ty * 4 + i) * PSTR + kk];
            float4 v0 = *(float4*)&Vs[kk * QSTR + tx * 8];
            float4 v1 = *(float4*)&Vs[kk * QSTR + tx * 8 + 4];
#pragma unroll
            for (int i = 0; i < 4; i++) {
                o[i][0] += p[i] * v0.x;  o[i][1] += p[i] * v0.y;
                o[i][2] += p[i] * v0.z;  o[i][3] += p[i] * v0.w;
                o[i][4] += p[i] * v1.x;  o[i][5] += p[i] * v1.y;
                o[i][6] += p[i] * v1.z;  o[i][7] += p[i] * v1.w;
            }
        }
    }

    // Write y in [B,T,C] layout (re-interleaving heads)
    const int b = bh >> 4;
    const int h = bh & 15;
#pragma unroll
    for (int i = 0; i < 4; i++) {
        float inv = 1.0f / l_i[i];
        int tq = qt * BQ + ty * 4 + i;
        size_t rowbase = ((size_t)(b * TT + tq)) * CC + h * HD + tx * 8;
        float4 r0, r1;
        r0.x = o[i][0] * inv; r0.y = o[i][1] * inv;
        r0.z = o[i][2] * inv; r0.w = o[i][3] * inv;
        r1.x = o[i][4] * inv; r1.y = o[i][5] * inv;
        r1.z = o[i][6] * inv; r1.w = o[i][7] * inv;
        *(float4*)&y[rowbase]     = r0;
        *(float4*)&y[rowbase + 4] = r1;
    }
}

// ---------------------------------------------------------------------------
extern "C" void kernel_launch(void* const* d_in, const int* in_sizes, int n_in,
                              void* d_out, int out_size)
{
    const float* x      = (const float*)d_in[0];
    const float* w_attn = (const float*)d_in[1];
    const float* w_proj = (const float*)d_in[2];
    const float* b_proj = (const float*)d_in[3];
    float* out = (float*)d_out;

    float *q, *k, *v, *y;
    cudaGetSymbolAddress((void**)&q, g_q);
    cudaGetSymbolAddress((void**)&k, g_k);
    cudaGetSymbolAddress((void**)&v, g_v);
    cudaGetSymbolAddress((void**)&y, g_y);

    cudaFuncSetAttribute(flash_attn, cudaFuncAttributeMaxDynamicSharedMemorySize,
                         FLASH_SMEM);

    // 1) QKV projection: [4096,2048] x [6144,2048]^T, scatter to q/k/v
    sgemm_qkv<<<dim3(N1 / BN, M1 / BM), 256>>>(x, w_attn, q, k, v);

    // 2) Causal flash attention
    flash_attn<<<dim3(TT / BQ, BB * HH), 256, FLASH_SMEM>>>(q, k, v, y);

    // 3) Output projection + bias
    sgemm_proj<<<dim3(CC / BN, M1 / BM), 256>>>(y, w_proj, b_proj, out);
}

// round 2
// speedup vs baseline: 1.5298x; 1.5298x over previous
#include <cuda_runtime.h>
#include <cuda_bf16.h>
#include <cstdint>

// Problem constants
#define BB 2
#define TT 2048
#define CC 2048
#define HH 16
#define HD 128
#define M1 (BB*TT)      // 4096
#define N1 (3*CC)       // 6144
#define K1 CC           // 2048

// Scratch (device globals; no allocation allowed)
__device__ float g_q[BB*HH*TT*HD];
__device__ float g_k[BB*HH*TT*HD];
__device__ float g_v[BB*HH*TT*HD];
__device__ float g_y[BB*TT*CC];

// ---------------------------------------------------------------------------
// bf16-split tensor-core GEMM: C = A(MxK row-major) * W(NxK row-major)^T
// Each fp32 operand is split into bf16 hi + lo; C = hi*hi + hi*lo + lo*hi.
// Block 128x128x32, 8 warps (2x4), warp tile 64x32, mma.m16n8k16.bf16.
// ---------------------------------------------------------------------------
#define GBM 128
#define GBN 128
#define GBK 32
#define SKS 40            // smem row stride in bf16 (32 + 8 pad => 48B rows)

__device__ __forceinline__ uint32_t smem_u32(const void* p) {
    return (uint32_t)__cvta_generic_to_shared(p);
}

__device__ __forceinline__ void ldsm_x4(uint32_t& r0, uint32_t& r1,
                                        uint32_t& r2, uint32_t& r3, uint32_t addr) {
    asm volatile("ldmatrix.sync.aligned.m8n8.x4.shared.b16 {%0,%1,%2,%3}, [%4];\n"
                 : "=r"(r0), "=r"(r1), "=r"(r2), "=r"(r3) : "r"(addr));
}

__device__ __forceinline__ void mma_bf16(float* c,
                                         uint32_t a0, uint32_t a1, uint32_t a2, uint32_t a3,
                                         uint32_t b0, uint32_t b1) {
    asm volatile("mma.sync.aligned.m16n8k16.row.col.f32.bf16.bf16.f32 "
                 "{%0,%1,%2,%3}, {%4,%5,%6,%7}, {%8,%9}, {%0,%1,%2,%3};\n"
                 : "+f"(c[0]), "+f"(c[1]), "+f"(c[2]), "+f"(c[3])
                 : "r"(a0), "r"(a1), "r"(a2), "r"(a3), "r"(b0), "r"(b1));
}

// Split two fp32 into packed bf16x2 hi and lo
__device__ __forceinline__ void split2(float x, float y, uint32_t& hi, uint32_t& lo) {
    __nv_bfloat162 h = __floats2bfloat162_rn(x, y);
    float hx = __bfloat162float(h.x);
    float hy = __bfloat162float(h.y);
    __nv_bfloat162 l = __floats2bfloat162_rn(x - hx, y - hy);
    hi = *(uint32_t*)&h;
    lo = *(uint32_t*)&l;
}

// EPI: 0 = qkv scatter into [B,H,T,HD] q/k/v; 1 = row-major out + bias
template<int EPI>
__global__ __launch_bounds__(256, 2)
void gemm_bf16split(const float* __restrict__ A, const float* __restrict__ W,
                    int Kd, int Nd,
                    float* __restrict__ o0, float* __restrict__ o1,
                    float* __restrict__ o2, const float* __restrict__ bias)
{
    __shared__ __align__(16) __nv_bfloat16 Ah[GBM][SKS];
    __shared__ __align__(16) __nv_bfloat16 Al[GBM][SKS];
    __shared__ __align__(16) __nv_bfloat16 Bh[GBN][SKS];
    __shared__ __align__(16) __nv_bfloat16 Bl[GBN][SKS];

    const int tid  = threadIdx.x;
    const int lane = tid & 31;
    const int wid  = tid >> 5;
    const int wm   = wid >> 2;      // 0..1
    const int wn   = wid & 3;       // 0..3
    const int m0   = blockIdx.y * GBM;
    const int n0   = blockIdx.x * GBN;

    float c[4][4][4];
#pragma unroll
    for (int mt = 0; mt < 4; mt++)
#pragma unroll
        for (int nt = 0; nt < 4; nt++)
#pragma unroll
            for (int r = 0; r < 4; r++) c[mt][nt][r] = 0.0f;

    const int lr = tid >> 3;          // 0..31 (row base for loads)
    const int lc = (tid & 7) * 4;     // fp32 col (0..28 step 4)

    // ldmatrix per-lane addressing (same for A and B tiles)
    const int lm_row = lane & 15;           // row within 16-row group
    const int lm_kc  = (lane >> 4) << 3;    // 0 or 8 (k chunk)

    for (int kt = 0; kt < Kd; kt += GBK) {
        __syncthreads();
#pragma unroll
        for (int i = 0; i < 4; i++) {
            int r = lr + i * 32;
            float4 av = *(const float4*)&A[(size_t)(m0 + r) * Kd + kt + lc];
            uint32_t h0, l0, h1, l1;
            split2(av.x, av.y, h0, l0);
            split2(av.z, av.w, h1, l1);
            *(uint32_t*)&Ah[r][lc]     = h0;  *(uint32_t*)&Ah[r][lc + 2] = h1;
            *(uint32_t*)&Al[r][lc]     = l0;  *(uint32_t*)&Al[r][lc + 2] = l1;
            float4 bv = *(const float4*)&W[(size_t)(n0 + r) * Kd + kt + lc];
            split2(bv.x, bv.y, h0, l0);
            split2(bv.z, bv.w, h1, l1);
            *(uint32_t*)&Bh[r][lc]     = h0;  *(uint32_t*)&Bh[r][lc + 2] = h1;
            *(uint32_t*)&Bl[r][lc]     = l0;  *(uint32_t*)&Bl[r][lc + 2] = l1;
        }
        __syncthreads();

#pragma unroll
        for (int ks = 0; ks < GBK; ks += 16) {
            // B fragments: 4 n-tiles (two 16-wide ldmatrix groups), hi & lo
            uint32_t bh[4][2], bl[4][2];
#pragma unroll
            for (int p = 0; p < 2; p++) {
                uint32_t r0, r1, r2, r3;
                int nrow = wn * 32 + p * 16 + lm_row;
                ldsm_x4(r0, r1, r2, r3, smem_u32(&Bh[nrow][ks + lm_kc]));
                bh[2*p][0] = r0; bh[2*p+1][0] = r1;
                bh[2*p][1] = r2; bh[2*p+1][1] = r3;
                ldsm_x4(r0, r1, r2, r3, smem_u32(&Bl[nrow][ks + lm_kc]));
                bl[2*p][0] = r0; bl[2*p+1][0] = r1;
                bl[2*p][1] = r2; bl[2*p+1][1] = r3;
            }
#pragma unroll
            for (int mt = 0; mt < 4; mt++) {
                uint32_t a0, a1, a2, a3, e0, e1, e2, e3;
                int mrow = wm * 64 + mt * 16 + lm_row;
                ldsm_x4(a0, a1, a2, a3, smem_u32(&Ah[mrow][ks + lm_kc]));
                ldsm_x4(e0, e1, e2, e3, smem_u32(&Al[mrow][ks + lm_kc]));
#pragma unroll
                for (int nt = 0; nt < 4; nt++) {
                    mma_bf16(c[mt][nt], a0, a1, a2, a3, bh[nt][0], bh[nt][1]); // hi*hi
                    mma_bf16(c[mt][nt], a0, a1, a2, a3, bl[nt][0], bl[nt][1]); // hi*lo
                    mma_bf16(c[mt][nt], e0, e1, e2, e3, bh[nt][0], bh[nt][1]); // lo*hi
                }
            }
        }
    }

    // Epilogue
    const int lrow = lane >> 2;
    const int lcol = (lane & 3) << 1;
#pragma unroll
    for (int mt = 0; mt < 4; mt++) {
        int mbase = m0 + wm * 64 + mt * 16 + lrow;
#pragma unroll
        for (int nt = 0; nt < 4; nt++) {
            int nbase = n0 + wn * 32 + nt * 8 + lcol;
#pragma unroll
            for (int s = 0; s < 2; s++) {
                int m = mbase + s * 8;
                if (EPI == 0) {
                    int bb = m >> 11;
                    int t  = m & 2047;
#pragma unroll
                    for (int e = 0; e < 2; e++) {
                        int n     = nbase + e;
                        int which = n >> 11;
                        int cidx  = n & 2047;
                        int h     = cidx >> 7;
                        int d     = cidx & 127;
                        float* dst = (which == 0) ? o0 : ((which == 1) ? o1 : o2);
                        dst[(((size_t)(bb * HH + h)) * TT + t) * HD + d] = c[mt][nt][s * 2 + e];
                    }
                } else {
                    float2 v;
                    v.x = c[mt][nt][s * 2 + 0] + bias[nbase];
                    v.y = c[mt][nt][s * 2 + 1] + bias[nbase + 1];
                    *(float2*)&o0[(size_t)m * Nd + nbase] = v;
                }
            }
        }
    }
}

// ---------------------------------------------------------------------------
// Flash attention (fp32, causal). BQ=64, BKV=64, D=128. 256 threads (16x16).
// ---------------------------------------------------------------------------
#define BQ 64
#define BKV 64
#define QSTR 132
#define PSTR 68
#define FLASH_SMEM ((BQ*QSTR*3 + BQ*PSTR) * 4)

__global__ __launch_bounds__(256, 1)
void flash_attn(const float* __restrict__ q, const float* __restrict__ k,
                const float* __restrict__ v, float* __restrict__ y)
{
    extern __shared__ float smem[];
    float* Qs = smem;
    float* Ks = Qs + BQ * QSTR;
    float* Vs = Ks + BQ * QSTR;
    float* Ps = Vs + BQ * QSTR;

    const int qt  = blockIdx.x;
    const int bh  = blockIdx.y;
    const int tid = threadIdx.x;
    const int tx  = tid & 15;
    const int ty  = tid >> 4;
    const float scale = 0.08838834764831845f;

    const size_t base = (size_t)bh * TT * HD;

#pragma unroll
    for (int it = 0; it < 8; it++) {
        int idx = tid + it * 256;
        int r   = idx >> 5;
        int d4  = (idx & 31) * 4;
        *(float4*)&Qs[r * QSTR + d4] =
            *(const float4*)&q[base + (size_t)(qt * BQ + r) * HD + d4];
    }

    float m_i[4], l_i[4], o[4][8];
#pragma unroll
    for (int i = 0; i < 4; i++) {
        m_i[i] = -1e30f;
        l_i[i] = 0.0f;
#pragma unroll
        for (int j = 0; j < 8; j++) o[i][j] = 0.0f;
    }

    const int nkt = qt + 1;
    for (int jt = 0; jt < nkt; jt++) {
        __syncthreads();

#pragma unroll
        for (int it = 0; it < 8; it++) {
            int idx = tid + it * 256;
            int r   = idx >> 5;
            int d4  = (idx & 31) * 4;
            size_t g = base + (size_t)(jt * BKV + r) * HD + d4;
            *(float4*)&Ks[r * QSTR + d4] = *(const float4*)&k[g];
            *(float4*)&Vs[r * QSTR + d4] = *(const float4*)&v[g];
        }
        __syncthreads();

        float s[4][4];
#pragma unroll
        for (int i = 0; i < 4; i++)
#pragma unroll
            for (int j = 0; j < 4; j++) s[i][j] = 0.0f;

        for (int d4 = 0; d4 < HD; d4 += 4) {
            float4 qv[4], kv[4];
#pragma unroll
            for (int i = 0; i < 4; i++)
                qv[i] = *(float4*)&Qs[(ty * 4 + i) * QSTR + d4];
#pragma unroll
            for (int j = 0; j < 4; j++)
                kv[j] = *(float4*)&Ks[(tx * 4 + j) * QSTR + d4];
#pragma unroll
            for (int i = 0; i < 4; i++)
#pragma unroll
                for (int j = 0; j < 4; j++) {
                    s[i][j] += qv[i].x * kv[j].x;
                    s[i][j] += qv[i].y * kv[j].y;
                    s[i][j] += qv[i].z * kv[j].z;
                    s[i][j] += qv[i].w * kv[j].w;
                }
        }

        const bool diag = (jt == qt);
#pragma unroll
        for (int i = 0; i < 4; i++) {
            int qg = qt * BQ + ty * 4 + i;
#pragma unroll
            for (int j = 0; j < 4; j++) {
                int kg = jt * BKV + tx * 4 + j;
                s[i][j] *= scale;
                if (diag && kg > qg) s[i][j] = -1e30f;
            }
        }

#pragma unroll
        for (int i = 0; i < 4; i++) {
            float mx = fmaxf(fmaxf(s[i][0], s[i][1]), fmaxf(s[i][2], s[i][3]));
#pragma unroll
            for (int off = 8; off >= 1; off >>= 1)
                mx = fmaxf(mx, __shfl_xor_sync(0xffffffffu, mx, off, 16));
            float mnew = fmaxf(m_i[i], mx);
            float corr = __expf(m_i[i] - mnew);
            float rs = 0.0f;
#pragma unroll
            for (int j = 0; j < 4; j++) {
                s[i][j] = __expf(s[i][j] - mnew);
                rs += s[i][j];
            }
#pragma unroll
            for (int off = 8; off >= 1; off >>= 1)
                rs += __shfl_xor_sync(0xffffffffu, rs, off, 16);
            l_i[i] = l_i[i] * corr + rs;
            m_i[i] = mnew;
#pragma unroll
            for (int jc = 0; jc < 8; jc++) o[i][jc] *= corr;
#pragma unroll
            for (int j = 0; j < 4; j++)
                Ps[(ty * 4 + i) * PSTR + tx * 4 + j] = s[i][j];
        }
        __syncthreads();

        for (int kk = 0; kk < BKV; kk++) {
            float p[4];
#pragma unroll
            for (int i = 0; i < 4; i++)
                p[i] = Ps[(ty * 4 + i) * PSTR + kk];
            float4 v0 = *(float4*)&Vs[kk * QSTR + tx * 8];
            float4 v1 = *(float4*)&Vs[kk * QSTR + tx * 8 + 4];
#pragma unroll
            for (int i = 0; i < 4; i++) {
                o[i][0] += p[i] * v0.x;  o[i][1] += p[i] * v0.y;
                o[i][2] += p[i] * v0.z;  o[i][3] += p[i] * v0.w;
                o[i][4] += p[i] * v1.x;  o[i][5] += p[i] * v1.y;
                o[i][6] += p[i] * v1.z;  o[i][7] += p[i] * v1.w;
            }
        }
    }

    const int b = bh >> 4;
    const int h = bh & 15;
#pragma unroll
    for (int i = 0; i < 4; i++) {
        float inv = 1.0f / l_i[i];
        int tq = qt * BQ + ty * 4 + i;
        size_t rowbase = ((size_t)(b * TT + tq)) * CC + h * HD + tx * 8;
        float4 r0, r1;
        r0.x = o[i][0] * inv; r0.y = o[i][1] * inv;
        r0.z = o[i][2] * inv; r0.w = o[i][3] * inv;
        r1.x = o[i][4] * inv; r1.y = o[i][5] * inv;
        r1.z = o[i][6] * inv; r1.w = o[i][7] * inv;
        *(float4*)&y[rowbase]     = r0;
        *(float4*)&y[rowbase + 4] = r1;
    }
}

// ---------------------------------------------------------------------------
extern "C" void kernel_launch(void* const* d_in, const int* in_sizes, int n_in,
                              void* d_out, int out_size)
{
    const float* x      = (const float*)d_in[0];
    const float* w_attn = (const float*)d_in[1];
    const float* w_proj = (const float*)d_in[2];
    const float* b_proj = (const float*)d_in[3];
    float* out = (float*)d_out;

    float *q, *k, *v, *y;
    cudaGetSymbolAddress((void**)&q, g_q);
    cudaGetSymbolAddress((void**)&k, g_k);
    cudaGetSymbolAddress((void**)&v, g_v);
    cudaGetSymbolAddress((void**)&y, g_y);

    cudaFuncSetAttribute(flash_attn, cudaFuncAttributeMaxDynamicSharedMemorySize,
                         FLASH_SMEM);

    // 1) QKV projection (tensor cores, bf16 split)
    gemm_bf16split<0><<<dim3(N1 / GBN, M1 / GBM), 256>>>(
        x, w_attn, K1, N1, q, k, v, nullptr);

    // 2) Causal flash attention
    flash_attn<<<dim3(TT / BQ, BB * HH), 256, FLASH_SMEM>>>(q, k, v, y);

    // 3) Output projection + bias (tensor cores, bf16 split)
    gemm_bf16split<1><<<dim3(CC / GBN, M1 / GBM), 256>>>(
        y, w_proj, K1, CC, out, nullptr, nullptr, b_proj);
}

// round 3
// speedup vs baseline: 2.8577x; 1.8680x over previous
#include <cuda_runtime.h>
#include <cuda_bf16.h>
#include <cstdint>

#define BB 2
#define TT 2048
#define CC 2048
#define HH 16
#define HD 128
#define M1 (BB*TT)      // 4096
#define N1 (3*CC)       // 6144
#define K1 CC           // 2048

// ---------------- device scratch (bf16 hi/lo pairs) ----------------
__device__ __nv_bfloat16 g_xh[M1*K1],  g_xl[M1*K1];
__device__ __nv_bfloat16 g_wah[N1*K1], g_wal[N1*K1];
__device__ __nv_bfloat16 g_wph[CC*CC], g_wpl[CC*CC];
__device__ __nv_bfloat16 g_qh[BB*HH*TT*HD], g_ql[BB*HH*TT*HD];
__device__ __nv_bfloat16 g_kh[BB*HH*TT*HD], g_kl[BB*HH*TT*HD];
__device__ __nv_bfloat16 g_vh[BB*HH*TT*HD], g_vl[BB*HH*TT*HD];
__device__ __nv_bfloat16 g_yh[M1*CC], g_yl[M1*CC];

// ---------------- helpers ----------------
__device__ __forceinline__ uint32_t smem_u32(const void* p) {
    return (uint32_t)__cvta_generic_to_shared(p);
}
__device__ __forceinline__ void ldsm_x4(uint32_t& r0, uint32_t& r1,
                                        uint32_t& r2, uint32_t& r3, uint32_t addr) {
    asm volatile("ldmatrix.sync.aligned.m8n8.x4.shared.b16 {%0,%1,%2,%3}, [%4];\n"
                 : "=r"(r0), "=r"(r1), "=r"(r2), "=r"(r3) : "r"(addr));
}
__device__ __forceinline__ void ldsm_x4t(uint32_t& r0, uint32_t& r1,
                                         uint32_t& r2, uint32_t& r3, uint32_t addr) {
    asm volatile("ldmatrix.sync.aligned.m8n8.x4.trans.shared.b16 {%0,%1,%2,%3}, [%4];\n"
                 : "=r"(r0), "=r"(r1), "=r"(r2), "=r"(r3) : "r"(addr));
}
__device__ __forceinline__ void mma_bf16(float* c,
                                         uint32_t a0, uint32_t a1, uint32_t a2, uint32_t a3,
                                         uint32_t b0, uint32_t b1) {
    asm volatile("mma.sync.aligned.m16n8k16.row.col.f32.bf16.bf16.f32 "
                 "{%0,%1,%2,%3}, {%4,%5,%6,%7}, {%8,%9}, {%0,%1,%2,%3};\n"
                 : "+f"(c[0]), "+f"(c[1]), "+f"(c[2]), "+f"(c[3])
                 : "r"(a0), "r"(a1), "r"(a2), "r"(a3), "r"(b0), "r"(b1));
}
__device__ __forceinline__ void split2(float x, float y, uint32_t& hi, uint32_t& lo) {
    __nv_bfloat162 h = __floats2bfloat162_rn(x, y);
    float hx = __bfloat162float(h.x);
    float hy = __bfloat162float(h.y);
    __nv_bfloat162 l = __floats2bfloat162_rn(x - hx, y - hy);
    hi = *(uint32_t*)&h;
    lo = *(uint32_t*)&l;
}
__device__ __forceinline__ void cp16(uint32_t saddr, const void* g) {
    asm volatile("cp.async.cg.shared.global [%0], [%1], 16;\n" :: "r"(saddr), "l"(g));
}
#define CP_COMMIT() asm volatile("cp.async.commit_group;\n" ::: "memory")
#define CP_WAIT(N)  asm volatile("cp.async.wait_group %0;\n" :: "n"(N) : "memory")

// ---------------- fp32 -> bf16 hi/lo split ----------------
__global__ void split_fp32(const float* __restrict__ in,
                           uint32_t* __restrict__ hi, uint32_t* __restrict__ lo, int n4)
{
    int i = blockIdx.x * blockDim.x + threadIdx.x;
    if (i >= n4) return;
    float4 v = ((const float4*)in)[i];
    uint32_t h0, l0, h1, l1;
    split2(v.x, v.y, h0, l0);
    split2(v.z, v.w, h1, l1);
    hi[i*2] = h0; hi[i*2+1] = h1;
    lo[i*2] = l0; lo[i*2+1] = l1;
}

// ---------------------------------------------------------------------------
// GEMM: C = A(MxK) * W(NxK)^T with pre-split bf16 hi/lo inputs.
// 128x128x32 tile, 8 warps, cp.async double-buffered.
// EPI 0: scatter qkv as scaled/split bf16 hi/lo; EPI 1: fp32 out + bias.
// ---------------------------------------------------------------------------
#define GSK 40
#define GTSZ (128*GSK)
#define GEMM_SMEM (2*4*GTSZ*2)   // 2 stages * 4 tiles * 128*40 bf16

template<int EPI>
__global__ __launch_bounds__(256, 2)
void gemm_pre(const __nv_bfloat16* __restrict__ Ah, const __nv_bfloat16* __restrict__ Al,
              const __nv_bfloat16* __restrict__ Wh, const __nv_bfloat16* __restrict__ Wl,
              int Kd, int Nd,
              __nv_bfloat16* o0h, __nv_bfloat16* o0l,
              __nv_bfloat16* o1h, __nv_bfloat16* o1l,
              __nv_bfloat16* o2h, __nv_bfloat16* o2l,
              float* fout, const float* __restrict__ bias)
{
    extern __shared__ __nv_bfloat16 gs[];

    const int tid  = threadIdx.x;
    const int lane = tid & 31;
    const int wid  = tid >> 5;
    const int wm   = wid >> 2;
    const int wn   = wid & 3;
    const int m0   = blockIdx.y * 128;
    const int n0   = blockIdx.x * 128;

    float c[4][4][4];
#pragma unroll
    for (int mt = 0; mt < 4; mt++)
#pragma unroll
        for (int nt = 0; nt < 4; nt++)
#pragma unroll
            for (int r = 0; r < 4; r++) c[mt][nt][r] = 0.0f;

    const int lm_row = lane & 15;
    const int lm_kc  = (lane >> 4) << 3;

    auto issue = [&](int s, int kt) {
        __nv_bfloat16* t0 = gs + (s*4 + 0) * GTSZ;
        __nv_bfloat16* t1 = gs + (s*4 + 1) * GTSZ;
        __nv_bfloat16* t2 = gs + (s*4 + 2) * GTSZ;
        __nv_bfloat16* t3 = gs + (s*4 + 3) * GTSZ;
#pragma unroll
        for (int half = 0; half < 2; half++) {
            int idx = tid + half * 256;
            int r   = idx >> 2;
            int c8  = (idx & 3) * 8;
            size_t ga = (size_t)(m0 + r) * Kd + /*kt*/ kt + c8;
            size_t gb = (size_t)(n0 + r) * Kd + kt + c8;
            uint32_t so = (uint32_t)(r * GSK + c8);
            cp16(smem_u32(t0 + so), Ah + ga);
            cp16(smem_u32(t1 + so), Al + ga);
            cp16(smem_u32(t2 + so), Wh + gb);
            cp16(smem_u32(t3 + so), Wl + gb);
        }
    };

    const int nk = Kd / 32;
    issue(0, 0);
    CP_COMMIT();

    for (int i = 0; i < nk; i++) {
        if (i + 1 < nk) {
            issue((i + 1) & 1, (i + 1) * 32);
            CP_COMMIT();
            CP_WAIT(1);
        } else {
            CP_WAIT(0);
        }
        __syncthreads();

        int s = i & 1;
        const __nv_bfloat16* sAh = gs + (s*4 + 0) * GTSZ;
        const __nv_bfloat16* sAl = gs + (s*4 + 1) * GTSZ;
        const __nv_bfloat16* sBh = gs + (s*4 + 2) * GTSZ;
        const __nv_bfloat16* sBl = gs + (s*4 + 3) * GTSZ;

#pragma unroll
        for (int ks = 0; ks < 32; ks += 16) {
            uint32_t bh[4][2], bl[4][2];
#pragma unroll
            for (int p = 0; p < 2; p++) {
                uint32_t r0, r1, r2, r3;
                int nrow = wn * 32 + p * 16 + lm_row;
                ldsm_x4(r0, r1, r2, r3, smem_u32(sBh + nrow*GSK + ks + lm_kc));
                bh[2*p][0] = r0; bh[2*p+1][0] = r1;
                bh[2*p][1] = r2; bh[2*p+1][1] = r3;
                ldsm_x4(r0, r1, r2, r3, smem_u32(sBl + nrow*GSK + ks + lm_kc));
                bl[2*p][0] = r0; bl[2*p+1][0] = r1;
                bl[2*p][1] = r2; bl[2*p+1][1] = r3;
            }
#pragma unroll
            for (int mt = 0; mt < 4; mt++) {
                uint32_t a0, a1, a2, a3, e0, e1, e2, e3;
                int mrow = wm * 64 + mt * 16 + lm_row;
                ldsm_x4(a0, a1, a2, a3, smem_u32(sAh + mrow*GSK + ks + lm_kc));
                ldsm_x4(e0, e1, e2, e3, smem_u32(sAl + mrow*GSK + ks + lm_kc));
#pragma unroll
                for (int nt = 0; nt < 4; nt++) {
                    mma_bf16(c[mt][nt], a0, a1, a2, a3, bh[nt][0], bh[nt][1]);
                    mma_bf16(c[mt][nt], a0, a1, a2, a3, bl[nt][0], bl[nt][1]);
                    mma_bf16(c[mt][nt], e0, e1, e2, e3, bh[nt][0], bh[nt][1]);
                }
            }
        }
        __syncthreads();
    }

    // epilogue
    const int lrow = lane >> 2;
    const int lcol = (lane & 3) << 1;
    const float qscale = 0.08838834764831845f;  // 1/sqrt(128)
#pragma unroll
    for (int mt = 0; mt < 4; mt++) {
        int mbase = m0 + wm * 64 + mt * 16 + lrow;
#pragma unroll
        for (int nt = 0; nt < 4; nt++) {
            int nbase = n0 + wn * 32 + nt * 8 + lcol;
#pragma unroll
            for (int sI = 0; sI < 2; sI++) {
                int m = mbase + sI * 8;
                float v0 = c[mt][nt][sI*2 + 0];
                float v1 = c[mt][nt][sI*2 + 1];
                if (EPI == 0) {
                    int bb = m >> 11;
                    int t  = m & 2047;
                    int which = nbase >> 11;      // pair never crosses (nbase even)
                    int cidx  = nbase & 2047;
                    int h     = cidx >> 7;
                    int d     = cidx & 127;
                    if (which == 0) { v0 *= qscale; v1 *= qscale; }
                    uint32_t hi, lo;
                    split2(v0, v1, hi, lo);
                    size_t idx = (((size_t)(bb * HH + h)) * TT + t) * HD + d;
                    __nv_bfloat16* dh = (which == 0) ? o0h : ((which == 1) ? o1h : o2h);
                    __nv_bfloat16* dl = (which == 0) ? o0l : ((which == 1) ? o1l : o2l);
                    *(uint32_t*)&dh[idx] = hi;
                    *(uint32_t*)&dl[idx] = lo;
                } else {
                    float2 w;
                    w.x = v0 + bias[nbase];
                    w.y = v1 + bias[nbase + 1];
                    *(float2*)&fout[(size_t)m * Nd + nbase] = w;
                }
            }
        }
    }
}

// ---------------------------------------------------------------------------
// Tensor-core flash attention, causal. BQ=128, BKV=64, HD=128, 8 warps.
// Q/K/V pre-split bf16 hi/lo; S and PV use 3-term split MMA; fp32 softmax.
// ---------------------------------------------------------------------------
#define FSTR 136
#define FLASH_SMEM ((2*128*FSTR + 4*64*FSTR) * 2)

__global__ __launch_bounds__(256, 1)
void flash_mma(const __nv_bfloat16* __restrict__ qh, const __nv_bfloat16* __restrict__ ql,
               const __nv_bfloat16* __restrict__ kh, const __nv_bfloat16* __restrict__ kl,
               const __nv_bfloat16* __restrict__ vh, const __nv_bfloat16* __restrict__ vl,
               __nv_bfloat16* __restrict__ yh, __nv_bfloat16* __restrict__ yl)
{
    extern __shared__ __nv_bfloat16 fs[];
    __nv_bfloat16* Qh = fs;
    __nv_bfloat16* Ql = Qh + 128 * FSTR;
    __nv_bfloat16* Kh = Ql + 128 * FSTR;
    __nv_bfloat16* Kl = Kh + 64 * FSTR;
    __nv_bfloat16* Vh = Kl + 64 * FSTR;
    __nv_bfloat16* Vl = Vh + 64 * FSTR;

    const int qt  = gridDim.x - 1 - blockIdx.x;   // heavy tiles first
    const int bh  = blockIdx.y;
    const int tid = threadIdx.x;
    const int lane = tid & 31;
    const int w    = tid >> 5;

    const size_t base = (size_t)bh * TT * HD;

    // load Q tile (128 x 128 bf16, hi+lo)
#pragma unroll
    for (int it = 0; it < 8; it++) {
        int idx = tid + it * 256;
        int r   = idx >> 4;
        int c8  = (idx & 15) * 8;
        size_t g = base + (size_t)(qt * 128 + r) * HD + c8;
        *(uint4*)&Qh[r * FSTR + c8] = *(const uint4*)&qh[g];
        *(uint4*)&Ql[r * FSTR + c8] = *(const uint4*)&ql[g];
    }

    float m0 = -1e30f, m1 = -1e30f, l0 = 0.0f, l1 = 0.0f;
    float co[16][4];
#pragma unroll
    for (int dt = 0; dt < 16; dt++)
#pragma unroll
        for (int r = 0; r < 4; r++) co[dt][r] = 0.0f;

    const int lm_row = lane & 15;
    const int lm_kc  = (lane >> 4) << 3;
    const int row0   = qt * 128 + w * 16 + (lane >> 2);

    const int nkt = 2 * qt + 2;
    for (int jt = 0; jt < nkt; jt++) {
        __syncthreads();
#pragma unroll
        for (int it = 0; it < 4; it++) {
            int idx = tid + it * 256;
            int r   = idx >> 4;
            int c8  = (idx & 15) * 8;
            size_t g = base + (size_t)(jt * 64 + r) * HD + c8;
            int so = r * FSTR + c8;
            *(uint4*)&Kh[so] = *(const uint4*)&kh[g];
            *(uint4*)&Kl[so] = *(const uint4*)&kl[g];
            *(uint4*)&Vh[so] = *(const uint4*)&vh[g];
            *(uint4*)&Vl[so] = *(const uint4*)&vl[g];
        }
        __syncthreads();

        // S = Q K^T  (m16 x n64 x k128 per warp, split 3-term)
        float s[8][4];
#pragma unroll
        for (int nt = 0; nt < 8; nt++)
#pragma unroll
            for (int r = 0; r < 4; r++) s[nt][r] = 0.0f;

#pragma unroll
        for (int kc = 0; kc < 8; kc++) {
            uint32_t a0, a1, a2, a3, e0, e1, e2, e3;
            int qrow = w * 16 + lm_row;
            ldsm_x4(a0, a1, a2, a3, smem_u32(Qh + qrow*FSTR + kc*16 + lm_kc));
            ldsm_x4(e0, e1, e2, e3, smem_u32(Ql + qrow*FSTR + kc*16 + lm_kc));
#pragma unroll
            for (int p = 0; p < 4; p++) {
                uint32_t r0, r1, r2, r3, u0, u1, u2, u3;
                int krow = p * 16 + lm_row;
                ldsm_x4(r0, r1, r2, r3, smem_u32(Kh + krow*FSTR + kc*16 + lm_kc));
                ldsm_x4(u0, u1, u2, u3, smem_u32(Kl + krow*FSTR + kc*16 + lm_kc));
                mma_bf16(s[2*p],   a0, a1, a2, a3, r0, r2);
                mma_bf16(s[2*p],   a0, a1, a2, a3, u0, u2);
                mma_bf16(s[2*p],   e0, e1, e2, e3, r0, r2);
                mma_bf16(s[2*p+1], a0, a1, a2, a3, r1, r3);
                mma_bf16(s[2*p+1], a0, a1, a2, a3, u1, u3);
                mma_bf16(s[2*p+1], e0, e1, e2, e3, r1, r3);
            }
        }

        // causal mask (only straddling tiles)
        if (jt * 64 + 63 > qt * 128 + w * 16) {
#pragma unroll
            for (int nt = 0; nt < 8; nt++) {
                int colb = jt * 64 + nt * 8 + (lane & 3) * 2;
#pragma unroll
                for (int e = 0; e < 2; e++) {
                    if (colb + e > row0)     s[nt][e]     = -1e30f;
                    if (colb + e > row0 + 8) s[nt][2 + e] = -1e30f;
                }
            }
        }

        // online softmax
        float mx0 = -1e30f, mx1 = -1e30f;
#pragma unroll
        for (int nt = 0; nt < 8; nt++) {
            mx0 = fmaxf(mx0, fmaxf(s[nt][0], s[nt][1]));
            mx1 = fmaxf(mx1, fmaxf(s[nt][2], s[nt][3]));
        }
        mx0 = fmaxf(mx0, __shfl_xor_sync(0xffffffffu, mx0, 1));
        mx0 = fmaxf(mx0, __shfl_xor_sync(0xffffffffu, mx0, 2));
        mx1 = fmaxf(mx1, __shfl_xor_sync(0xffffffffu, mx1, 1));
        mx1 = fmaxf(mx1, __shfl_xor_sync(0xffffffffu, mx1, 2));

        float mn0 = fmaxf(m0, mx0);
        float mn1 = fmaxf(m1, mx1);
        float cr0 = __expf(m0 - mn0);
        float cr1 = __expf(m1 - mn1);
        m0 = mn0; m1 = mn1;

        float rs0 = 0.0f, rs1 = 0.0f;
#pragma unroll
        for (int nt = 0; nt < 8; nt++) {
            s[nt][0] = __expf(s[nt][0] - mn0);
            s[nt][1] = __expf(s[nt][1] - mn0);
            s[nt][2] = __expf(s[nt][2] - mn1);
            s[nt][3] = __expf(s[nt][3] - mn1);
            rs0 += s[nt][0] + s[nt][1];
            rs1 += s[nt][2] + s[nt][3];
        }
        rs0 += __shfl_xor_sync(0xffffffffu, rs0, 1);
        rs0 += __shfl_xor_sync(0xffffffffu, rs0, 2);
        rs1 += __shfl_xor_sync(0xffffffffu, rs1, 1);
        rs1 += __shfl_xor_sync(0xffffffffu, rs1, 2);
        l0 = l0 * cr0 + rs0;
        l1 = l1 * cr1 + rs1;

#pragma unroll
        for (int dt = 0; dt < 16; dt++) {
            co[dt][0] *= cr0; co[dt][1] *= cr0;
            co[dt][2] *= cr1; co[dt][3] *= cr1;
        }

        // O += P V  (split P hi/lo; V hi/lo from trans-ldsm)
#pragma unroll
        for (int kc2 = 0; kc2 < 4; kc2++) {
            uint32_t ph[4], pl[4];
            split2(s[2*kc2][0],   s[2*kc2][1],   ph[0], pl[0]);
            split2(s[2*kc2][2],   s[2*kc2][3],   ph[1], pl[1]);
            split2(s[2*kc2+1][0], s[2*kc2+1][1], ph[2], pl[2]);
            split2(s[2*kc2+1][2], s[2*kc2+1][3], ph[3], pl[3]);
#pragma unroll
            for (int dp = 0; dp < 8; dp++) {
                uint32_t v0, v1, v2, v3, x0, x1, x2, x3;
                int vrow = kc2 * 16 + lm_row;
                ldsm_x4t(v0, v1, v2, v3, smem_u32(Vh + vrow*FSTR + dp*16 + lm_kc));
                ldsm_x4t(x0, x1, x2, x3, smem_u32(Vl + vrow*FSTR + dp*16 + lm_kc));
                mma_bf16(co[2*dp],   ph[0], ph[1], ph[2], ph[3], v0, v1);
                mma_bf16(co[2*dp],   pl[0], pl[1], pl[2], pl[3], v0, v1);
                mma_bf16(co[2*dp],   ph[0], ph[1], ph[2], ph[3], x0, x1);
                mma_bf16(co[2*dp+1], ph[0], ph[1], ph[2], ph[3], v2, v3);
                mma_bf16(co[2*dp+1], pl[0], pl[1], pl[2], pl[3], v2, v3);
                mma_bf16(co[2*dp+1], ph[0], ph[1], ph[2], ph[3], x2, x3);
            }
        }
    }

    // epilogue: y = O / l  -> split bf16 hi/lo in [B,T,C]
    const float inv0 = 1.0f / l0;
    const float inv1 = 1.0f / l1;
    const int b = bh >> 4;
    const int h = bh & 15;
    const int trow0 = row0;          // global query row
#pragma unroll
    for (int dt = 0; dt < 16; dt++) {
        int d = dt * 8 + (lane & 3) * 2;
        uint32_t hi, lo;
        size_t i0 = ((size_t)(b * TT + trow0)) * CC + h * HD + d;
        split2(co[dt][0] * inv0, co[dt][1] * inv0, hi, lo);
        *(uint32_t*)&yh[i0] = hi;
        *(uint32_t*)&yl[i0] = lo;
        size_t i1 = ((size_t)(b * TT + trow0 + 8)) * CC + h * HD + d;
        split2(co[dt][2] * inv1, co[dt][3] * inv1, hi, lo);
        *(uint32_t*)&yh[i1] = hi;
        *(uint32_t*)&yl[i1] = lo;
    }
}

// ---------------------------------------------------------------------------
extern "C" void kernel_launch(void* const* d_in, const int* in_sizes, int n_in,
                              void* d_out, int out_size)
{
    const float* x      = (const float*)d_in[0];
    const float* w_attn = (const float*)d_in[1];
    const float* w_proj = (const float*)d_in[2];
    const float* b_proj = (const float*)d_in[3];
    float* out = (float*)d_out;

    __nv_bfloat16 *xh, *xl, *wah, *wal, *wph, *wpl;
    __nv_bfloat16 *qh, *ql, *kh, *kl, *vh, *vl, *yh, *yl;
    cudaGetSymbolAddress((void**)&xh,  g_xh);  cudaGetSymbolAddress((void**)&xl,  g_xl);
    cudaGetSymbolAddress((void**)&wah, g_wah); cudaGetSymbolAddress((void**)&wal, g_wal);
    cudaGetSymbolAddress((void**)&wph, g_wph); cudaGetSymbolAddress((void**)&wpl, g_wpl);
    cudaGetSymbolAddress((void**)&qh,  g_qh);  cudaGetSymbolAddress((void**)&ql,  g_ql);
    cudaGetSymbolAddress((void**)&kh,  g_kh);  cudaGetSymbolAddress((void**)&kl,  g_kl);
    cudaGetSymbolAddress((void**)&vh,  g_vh);  cudaGetSymbolAddress((void**)&vl,  g_vl);
    cudaGetSymbolAddress((void**)&yh,  g_yh);  cudaGetSymbolAddress((void**)&yl,  g_yl);

    cudaFuncSetAttribute(gemm_pre<0>, cudaFuncAttributeMaxDynamicSharedMemorySize, GEMM_SMEM);
    cudaFuncSetAttribute(gemm_pre<1>, cudaFuncAttributeMaxDynamicSharedMemorySize, GEMM_SMEM);
    cudaFuncSetAttribute(flash_mma,   cudaFuncAttributeMaxDynamicSharedMemorySize, FLASH_SMEM);

    // 0) pre-split inputs
    split_fp32<<<(M1*K1/4 + 255)/256, 256>>>(x,      (uint32_t*)xh,  (uint32_t*)xl,  M1*K1/4);
    split_fp32<<<(N1*K1/4 + 255)/256, 256>>>(w_attn, (uint32_t*)wah, (uint32_t*)wal, N1*K1/4);
    split_fp32<<<(CC*CC/4 + 255)/256, 256>>>(w_proj, (uint32_t*)wph, (uint32_t*)wpl, CC*CC/4);

    // 1) QKV projection -> split q/k/v (q pre-scaled)
    gemm_pre<0><<<dim3(N1/128, M1/128), 256, GEMM_SMEM>>>(
        xh, xl, wah, wal, K1, N1, qh, ql, kh, kl, vh, vl, nullptr, nullptr);

    // 2) causal flash attention (tensor cores) -> split y
    flash_mma<<<dim3(TT/128, BB*HH), 256, FLASH_SMEM>>>(qh, ql, kh, kl, vh, vl, yh, yl);

    // 3) output projection + bias
    gemm_pre<1><<<dim3(CC/128, M1/128), 256, GEMM_SMEM>>>(
        yh, yl, wph, wpl, K1, CC, nullptr, nullptr, nullptr, nullptr, nullptr, nullptr,
        out, b_proj);
}

// round 5
// speedup vs baseline: 3.9425x; 1.3796x over previous
#include <cuda_runtime.h>
#include <cuda_bf16.h>
#include <cuda_fp16.h>
#include <cstdint>

#define BB 2
#define TT 2048
#define CC 2048
#define HH 16
#define HD 128
#define M1 (BB*TT)      // 4096
#define N1 (3*CC)       // 6144
#define K1 CC           // 2048

// ---------------- device scratch ----------------
__device__ __half g_x16[M1*K1];
__device__ __half g_wah16[N1*K1], g_wal16[N1*K1];
__device__ __half g_wph16[CC*CC], g_wpl16[CC*CC];
__device__ __nv_bfloat16 g_qh[BB*HH*TT*HD], g_ql[BB*HH*TT*HD];
__device__ __nv_bfloat16 g_kh[BB*HH*TT*HD], g_kl[BB*HH*TT*HD];
__device__ __nv_bfloat16 g_vh[BB*HH*TT*HD], g_vl[BB*HH*TT*HD];
__device__ __half g_y16[M1*CC];

// ---------------- helpers ----------------
__device__ __forceinline__ uint32_t smem_u32(const void* p) {
    return (uint32_t)__cvta_generic_to_shared(p);
}
__device__ __forceinline__ void ldsm_x4(uint32_t& r0, uint32_t& r1,
                                        uint32_t& r2, uint32_t& r3, uint32_t addr) {
    asm volatile("ldmatrix.sync.aligned.m8n8.x4.shared.b16 {%0,%1,%2,%3}, [%4];\n"
                 : "=r"(r0), "=r"(r1), "=r"(r2), "=r"(r3) : "r"(addr));
}
__device__ __forceinline__ void ldsm_x4t(uint32_t& r0, uint32_t& r1,
                                         uint32_t& r2, uint32_t& r3, uint32_t addr) {
    asm volatile("ldmatrix.sync.aligned.m8n8.x4.trans.shared.b16 {%0,%1,%2,%3}, [%4];\n"
                 : "=r"(r0), "=r"(r1), "=r"(r2), "=r"(r3) : "r"(addr));
}
__device__ __forceinline__ void mma_bf16(float* c,
                                         uint32_t a0, uint32_t a1, uint32_t a2, uint32_t a3,
                                         uint32_t b0, uint32_t b1) {
    asm volatile("mma.sync.aligned.m16n8k16.row.col.f32.bf16.bf16.f32 "
                 "{%0,%1,%2,%3}, {%4,%5,%6,%7}, {%8,%9}, {%0,%1,%2,%3};\n"
                 : "+f"(c[0]), "+f"(c[1]), "+f"(c[2]), "+f"(c[3])
                 : "r"(a0), "r"(a1), "r"(a2), "r"(a3), "r"(b0), "r"(b1));
}
__device__ __forceinline__ void mma_fp16(float* c,
                                         uint32_t a0, uint32_t a1, uint32_t a2, uint32_t a3,
                                         uint32_t b0, uint32_t b1) {
    asm volatile("mma.sync.aligned.m16n8k16.row.col.f32.f16.f16.f32 "
                 "{%0,%1,%2,%3}, {%4,%5,%6,%7}, {%8,%9}, {%0,%1,%2,%3};\n"
                 : "+f"(c[0]), "+f"(c[1]), "+f"(c[2]), "+f"(c[3])
                 : "r"(a0), "r"(a1), "r"(a2), "r"(a3), "r"(b0), "r"(b1));
}
__device__ __forceinline__ void split2(float x, float y, uint32_t& hi, uint32_t& lo) {
    __nv_bfloat162 h = __floats2bfloat162_rn(x, y);
    float hx = __bfloat162float(h.x);
    float hy = __bfloat162float(h.y);
    __nv_bfloat162 l = __floats2bfloat162_rn(x - hx, y - hy);
    hi = *(uint32_t*)&h;
    lo = *(uint32_t*)&l;
}
__device__ __forceinline__ void split2h(float x, float y, uint32_t& hi, uint32_t& lo) {
    __half2 h = __floats2half2_rn(x, y);
    float hx = __low2float(h);
    float hy = __high2float(h);
    __half2 l = __floats2half2_rn(x - hx, y - hy);
    hi = *(uint32_t*)&h;
    lo = *(uint32_t*)&l;
}
__device__ __forceinline__ void cp16(uint32_t saddr, const void* g) {
    asm volatile("cp.async.cg.shared.global [%0], [%1], 16;\n" :: "r"(saddr), "l"(g));
}
#define CP_COMMIT() asm volatile("cp.async.commit_group;\n" ::: "memory")
#define CP_WAIT(N)  asm volatile("cp.async.wait_group %0;\n" :: "n"(N) : "memory")

// ---------------- split kernels ----------------
__global__ void split_h(const float* __restrict__ in, uint32_t* __restrict__ hi, int n4)
{
    int i = blockIdx.x * blockDim.x + threadIdx.x;
    if (i >= n4) return;
    float4 v = ((const float4*)in)[i];
    __half2 h0 = __floats2half2_rn(v.x, v.y);
    __half2 h1 = __floats2half2_rn(v.z, v.w);
    hi[i*2]   = *(uint32_t*)&h0;
    hi[i*2+1] = *(uint32_t*)&h1;
}
__global__ void split_hl(const float* __restrict__ in,
                         uint32_t* __restrict__ hi, uint32_t* __restrict__ lo, int n4)
{
    int i = blockIdx.x * blockDim.x + threadIdx.x;
    if (i >= n4) return;
    float4 v = ((const float4*)in)[i];
    uint32_t h0, l0, h1, l1;
    split2h(v.x, v.y, h0, l0);
    split2h(v.z, v.w, h1, l1);
    hi[i*2] = h0; hi[i*2+1] = h1;
    lo[i*2] = l0; lo[i*2+1] = l1;
}

// ---------------------------------------------------------------------------
// fp16 2-term GEMM: C = A(MxK) * W(NxK)^T.  A single fp16; W split hi/lo.
// C = A*Wh + A*Wl.  128x128x32 tile, 8 warps, cp.async double-buffered.
// EPI 0: qkv scatter (scaled q, bf16 split); EPI 1: fp32 out + bias.
// ---------------------------------------------------------------------------
#define GSK 40
#define GTSZ (128*GSK)            // elems per tile
#define G_SMEM (2*3*GTSZ*2)       // 61440 bytes

template<int EPI>
__global__ __launch_bounds__(256, 2)
void gemm_fp16(const __half* __restrict__ A,
               const __half* __restrict__ Wh, const __half* __restrict__ Wl,
               int Kd, int Nd,
               __nv_bfloat16* o0h, __nv_bfloat16* o0l,
               __nv_bfloat16* o1h, __nv_bfloat16* o1l,
               __nv_bfloat16* o2h, __nv_bfloat16* o2l,
               float* fout, const float* __restrict__ bias)
{
    extern __shared__ __half gs[];

    const int tid  = threadIdx.x;
    const int lane = tid & 31;
    const int wid  = tid >> 5;
    const int wm   = wid >> 2;
    const int wn   = wid & 3;
    const int m0   = blockIdx.y * 128;
    const int n0   = blockIdx.x * 128;

    float c[4][4][4];
#pragma unroll
    for (int mt = 0; mt < 4; mt++)
#pragma unroll
        for (int nt = 0; nt < 4; nt++)
#pragma unroll
            for (int r = 0; r < 4; r++) c[mt][nt][r] = 0.0f;

    const int lm_row = lane & 15;
    const int lm_kc  = (lane >> 4) << 3;

    auto issue = [&](int s, int kt) {
        __half* stg = gs + s * 3 * GTSZ;
#pragma unroll
        for (int it = 0; it < 6; it++) {
            int g   = tid + it * 256;       // 0..1535
            int sel = g >> 9;               // 0=A, 1=Wh, 2=Wl
            int rem = g & 511;
            int row = rem >> 2;
            int col = (rem & 3) * 8;
            const __half* src = (sel == 0) ? (A  + (size_t)(m0 + row) * Kd + kt + col)
                             : ((sel == 1) ? (Wh + (size_t)(n0 + row) * Kd + kt + col)
                                           : (Wl + (size_t)(n0 + row) * Kd + kt + col));
            cp16(smem_u32(stg + sel * GTSZ + row * GSK + col), src);
        }
    };

    const int nk = Kd / 32;
    issue(0, 0);
    CP_COMMIT();

    for (int i = 0; i < nk; i++) {
        if (i + 1 < nk) {
            issue((i + 1) & 1, (i + 1) * 32);
            CP_COMMIT();
            CP_WAIT(1);
        } else {
            CP_WAIT(0);
        }
        __syncthreads();

        const __half* sA  = gs + (i & 1) * 3 * GTSZ;
        const __half* sBh = sA + GTSZ;
        const __half* sBl = sA + 2 * GTSZ;

#pragma unroll
        for (int ks = 0; ks < 32; ks += 16) {
            uint32_t bh[4][2], bl[4][2];
#pragma unroll
            for (int p = 0; p < 2; p++) {
                uint32_t r0, r1, r2, r3;
                int nrow = wn * 32 + p * 16 + lm_row;
                ldsm_x4(r0, r1, r2, r3, smem_u32(sBh + nrow*GSK + ks + lm_kc));
                bh[2*p][0] = r0; bh[2*p+1][0] = r1;
                bh[2*p][1] = r2; bh[2*p+1][1] = r3;
                ldsm_x4(r0, r1, r2, r3, smem_u32(sBl + nrow*GSK + ks + lm_kc));
                bl[2*p][0] = r0; bl[2*p+1][0] = r1;
                bl[2*p][1] = r2; bl[2*p+1][1] = r3;
            }
#pragma unroll
            for (int mt = 0; mt < 4; mt++) {
                uint32_t a0, a1, a2, a3;
                int mrow = wm * 64 + mt * 16 + lm_row;
                ldsm_x4(a0, a1, a2, a3, smem_u32(sA + mrow*GSK + ks + lm_kc));
#pragma unroll
                for (int nt = 0; nt < 4; nt++) {
                    mma_fp16(c[mt][nt], a0, a1, a2, a3, bh[nt][0], bh[nt][1]);
                    mma_fp16(c[mt][nt], a0, a1, a2, a3, bl[nt][0], bl[nt][1]);
                }
            }
        }
        __syncthreads();
    }

    // epilogue
    const int lrow = lane >> 2;
    const int lcol = (lane & 3) << 1;
    const float qscale = 0.08838834764831845f;  // 1/sqrt(128)
#pragma unroll
    for (int mt = 0; mt < 4; mt++) {
        int mbase = m0 + wm * 64 + mt * 16 + lrow;
#pragma unroll
        for (int nt = 0; nt < 4; nt++) {
            int nbase = n0 + wn * 32 + nt * 8 + lcol;
#pragma unroll
            for (int sI = 0; sI < 2; sI++) {
                int m = mbase + sI * 8;
                float v0 = c[mt][nt][sI*2 + 0];
                float v1 = c[mt][nt][sI*2 + 1];
                if (EPI == 0) {
                    int bb = m >> 11;
                    int t  = m & 2047;
                    int which = nbase >> 11;
                    int cidx  = nbase & 2047;
                    int h     = cidx >> 7;
                    int d     = cidx & 127;
                    if (which == 0) { v0 *= qscale; v1 *= qscale; }
                    uint32_t hi, lo;
                    split2(v0, v1, hi, lo);
                    size_t idx = (((size_t)(bb * HH + h)) * TT + t) * HD + d;
                    __nv_bfloat16* dh = (which == 0) ? o0h : ((which == 1) ? o1h : o2h);
                    __nv_bfloat16* dl = (which == 0) ? o0l : ((which == 1) ? o1l : o2l);
                    *(uint32_t*)&dh[idx] = hi;
                    *(uint32_t*)&dl[idx] = lo;
                } else {
                    float2 w;
                    w.x = v0 + bias[nbase];
                    w.y = v1 + bias[nbase + 1];
                    *(float2*)&fout[(size_t)m * Nd + nbase] = w;
                }
            }
        }
    }
}

// ---------------------------------------------------------------------------
// Tensor-core flash attention (mma.sync, bf16 3-term), causal.
// BQ=128, BKV=64, 8 warps. 2-stage cp.async on K/V. Output y fp16.
// ---------------------------------------------------------------------------
#define FSTR 136
#define FL_TILE (64*FSTR)
#define FL_STG  (4*FL_TILE)
#define FLASH_SMEM ((2*128*FSTR + 2*FL_STG) * 2)   // 208896 bytes

__global__ __launch_bounds__(256, 1)
void flash_mma(const __nv_bfloat16* __restrict__ qh, const __nv_bfloat16* __restrict__ ql,
               const __nv_bfloat16* __restrict__ kh, const __nv_bfloat16* __restrict__ kl,
               const __nv_bfloat16* __restrict__ vh, const __nv_bfloat16* __restrict__ vl,
               __half* __restrict__ y16)
{
    extern __shared__ __nv_bfloat16 fs[];
    __nv_bfloat16* Qh   = fs;
    __nv_bfloat16* Ql   = Qh + 128 * FSTR;
    __nv_bfloat16* stg0 = Ql + 128 * FSTR;

    const int qt  = gridDim.x - 1 - blockIdx.x;
    const int bh  = blockIdx.y;
    const int tid = threadIdx.x;
    const int lane = tid & 31;
    const int w    = tid >> 5;

    const size_t base = (size_t)bh * TT * HD;

#pragma unroll
    for (int it = 0; it < 8; it++) {
        int idx = tid + it * 256;
        int r   = idx >> 4;
        int c8  = (idx & 15) * 8;
        size_t g = base + (size_t)(qt * 128 + r) * HD + c8;
        *(uint4*)&Qh[r * FSTR + c8] = *(const uint4*)&qh[g];
        *(uint4*)&Ql[r * FSTR + c8] = *(const uint4*)&ql[g];
    }

    auto issue_kv = [&](int s, int jt) {
        __nv_bfloat16* sbase = stg0 + s * FL_STG;
#pragma unroll
        for (int it = 0; it < 16; it++) {
            int g   = tid + it * 256;     // 0..4095
            int sel = g >> 10;            // 0=Kh,1=Kl,2=Vh,3=Vl
            int rem = g & 1023;
            int row = rem >> 4;
            int c8  = (rem & 15) * 8;
            const __nv_bfloat16* src =
                (sel == 0) ? kh : ((sel == 1) ? kl : ((sel == 2) ? vh : vl));
            cp16(smem_u32(sbase + sel * FL_TILE + row * FSTR + c8),
                 src + base + (size_t)(jt * 64 + row) * HD + c8);
        }
    };

    float m0 = -1e30f, m1 = -1e30f, l0 = 0.0f, l1 = 0.0f;
    float co[16][4];
#pragma unroll
    for (int dt = 0; dt < 16; dt++)
#pragma unroll
        for (int r = 0; r < 4; r++) co[dt][r] = 0.0f;

    const int lm_row = lane & 15;
    const int lm_kc  = (lane >> 4) << 3;
    const int row0   = qt * 128 + w * 16 + (lane >> 2);

    const int nkt = 2 * qt + 2;
    issue_kv(0, 0);
    CP_COMMIT();

    for (int jt = 0; jt < nkt; jt++) {
        if (jt + 1 < nkt) {
            issue_kv((jt + 1) & 1, jt + 1);
            CP_COMMIT();
            CP_WAIT(1);
        } else {
            CP_WAIT(0);
        }
        __syncthreads();

        const __nv_bfloat16* Kh = stg0 + (jt & 1) * FL_STG;
        const __nv_bfloat16* Kl = Kh + FL_TILE;
        const __nv_bfloat16* Vh = Kh + 2 * FL_TILE;
        const __nv_bfloat16* Vl = Kh + 3 * FL_TILE;

        float s[8][4];
#pragma unroll
        for (int nt = 0; nt < 8; nt++)
#pragma unroll
            for (int r = 0; r < 4; r++) s[nt][r] = 0.0f;

#pragma unroll
        for (int kc = 0; kc < 8; kc++) {
            uint32_t a0, a1, a2, a3, e0, e1, e2, e3;
            int qrow = w * 16 + lm_row;
            ldsm_x4(a0, a1, a2, a3, smem_u32(Qh + qrow*FSTR + kc*16 + lm_kc));
            ldsm_x4(e0, e1, e2, e3, smem_u32(Ql + qrow*FSTR + kc*16 + lm_kc));
#pragma unroll
            for (int p = 0; p < 4; p++) {
                uint32_t r0, r1, r2, r3, u0, u1, u2, u3;
                int krow = p * 16 + lm_row;
                ldsm_x4(r0, r1, r2, r3, smem_u32(Kh + krow*FSTR + kc*16 + lm_kc));
                ldsm_x4(u0, u1, u2, u3, smem_u32(Kl + krow*FSTR + kc*16 + lm_kc));
                mma_bf16(s[2*p],   a0, a1, a2, a3, r0, r2);
                mma_bf16(s[2*p],   a0, a1, a2, a3, u0, u2);
                mma_bf16(s[2*p],   e0, e1, e2, e3, r0, r2);
                mma_bf16(s[2*p+1], a0, a1, a2, a3, r1, r3);
                mma_bf16(s[2*p+1], a0, a1, a2, a3, u1, u3);
                mma_bf16(s[2*p+1], e0, e1, e2, e3, r1, r3);
            }
        }

        if (jt * 64 + 63 > qt * 128 + w * 16) {
#pragma unroll
            for (int nt = 0; nt < 8; nt++) {
                int colb = jt * 64 + nt * 8 + (lane & 3) * 2;
#pragma unroll
                for (int e = 0; e < 2; e++) {
                    if (colb + e > row0)     s[nt][e]     = -1e30f;
                    if (colb + e > row0 + 8) s[nt][2 + e] = -1e30f;
                }
            }
        }

        float mx0 = -1e30f, mx1 = -1e30f;
#pragma unroll
        for (int nt = 0; nt < 8; nt++) {
            mx0 = fmaxf(mx0, fmaxf(s[nt][0], s[nt][1]));
            mx1 = fmaxf(mx1, fmaxf(s[nt][2], s[nt][3]));
        }
        mx0 = fmaxf(mx0, __shfl_xor_sync(0xffffffffu, mx0, 1));
        mx0 = fmaxf(mx0, __shfl_xor_sync(0xffffffffu, mx0, 2));
        mx1 = fmaxf(mx1, __shfl_xor_sync(0xffffffffu, mx1, 1));
        mx1 = fmaxf(mx1, __shfl_xor_sync(0xffffffffu, mx1, 2));

        float mn0 = fmaxf(m0, mx0);
        float mn1 = fmaxf(m1, mx1);
        float cr0 = __expf(m0 - mn0);
        float cr1 = __expf(m1 - mn1);
        m0 = mn0; m1 = mn1;

        float rs0 = 0.0f, rs1 = 0.0f;
#pragma unroll
        for (int nt = 0; nt < 8; nt++) {
            s[nt][0] = __expf(s[nt][0] - mn0);
            s[nt][1] = __expf(s[nt][1] - mn0);
            s[nt][2] = __expf(s[nt][2] - mn1);
            s[nt][3] = __expf(s[nt][3] - mn1);
            rs0 += s[nt][0] + s[nt][1];
            rs1 += s[nt][2] + s[nt][3];
        }
        rs0 += __shfl_xor_sync(0xffffffffu, rs0, 1);
        rs0 += __shfl_xor_sync(0xffffffffu, rs0, 2);
        rs1 += __shfl_xor_sync(0xffffffffu, rs1, 1);
        rs1 += __shfl_xor_sync(0xffffffffu, rs1, 2);
        l0 = l0 * cr0 + rs0;
        l1 = l1 * cr1 + rs1;

#pragma unroll
        for (int dt = 0; dt < 16; dt++) {
            co[dt][0] *= cr0; co[dt][1] *= cr0;
            co[dt][2] *= cr1; co[dt][3] *= cr1;
        }

#pragma unroll
        for (int kc2 = 0; kc2 < 4; kc2++) {
            uint32_t ph2[4], pl2[4];
            split2(s[2*kc2][0],   s[2*kc2][1],   ph2[0], pl2[0]);
            split2(s[2*kc2][2],   s[2*kc2][3],   ph2[1], pl2[1]);
            split2(s[2*kc2+1][0], s[2*kc2+1][1], ph2[2], pl2[2]);
            split2(s[2*kc2+1][2], s[2*kc2+1][3], ph2[3], pl2[3]);
#pragma unroll
            for (int dp = 0; dp < 8; dp++) {
                uint32_t v0, v1, v2, v3, x0, x1, x2, x3;
                int vrow = kc2 * 16 + lm_row;
                ldsm_x4t(v0, v1, v2, v3, smem_u32(Vh + vrow*FSTR + dp*16 + lm_kc));
                ldsm_x4t(x0, x1, x2, x3, smem_u32(Vl + vrow*FSTR + dp*16 + lm_kc));
                mma_bf16(co[2*dp],   ph2[0], ph2[1], ph2[2], ph2[3], v0, v1);
                mma_bf16(co[2*dp],   pl2[0], pl2[1], pl2[2], pl2[3], v0, v1);
                mma_bf16(co[2*dp],   ph2[0], ph2[1], ph2[2], ph2[3], x0, x1);
                mma_bf16(co[2*dp+1], ph2[0], ph2[1], ph2[2], ph2[3], v2, v3);
                mma_bf16(co[2*dp+1], pl2[0], pl2[1], pl2[2], pl2[3], v2, v3);
                mma_bf16(co[2*dp+1], ph2[0], ph2[1], ph2[2], ph2[3], x2, x3);
            }
        }
        __syncthreads();
    }

    const float inv0 = 1.0f / l0;
    const float inv1 = 1.0f / l1;
    const int b = bh >> 4;
    const int h = bh & 15;
#pragma unroll
    for (int dt = 0; dt < 16; dt++) {
        int d = dt * 8 + (lane & 3) * 2;
        size_t i0 = ((size_t)(b * TT + row0)) * CC + h * HD + d;
        __half2 p0 = __floats2half2_rn(co[dt][0] * inv0, co[dt][1] * inv0);
        *(uint32_t*)&y16[i0] = *(uint32_t*)&p0;
        size_t i1 = ((size_t)(b * TT + row0 + 8)) * CC + h * HD + d;
        __half2 p1 = __floats2half2_rn(co[dt][2] * inv1, co[dt][3] * inv1);
        *(uint32_t*)&y16[i1] = *(uint32_t*)&p1;
    }
}

// ---------------------------------------------------------------------------
extern "C" void kernel_launch(void* const* d_in, const int* in_sizes, int n_in,
                              void* d_out, int out_size)
{
    const float* x      = (const float*)d_in[0];
    const float* w_attn = (const float*)d_in[1];
    const float* w_proj = (const float*)d_in[2];
    const float* b_proj = (const float*)d_in[3];
    float* out = (float*)d_out;

    __half *x16, *wah, *wal, *wph, *wpl, *y16;
    __nv_bfloat16 *qh, *ql, *kh, *kl, *vh, *vl;
    cudaGetSymbolAddress((void**)&x16, g_x16);
    cudaGetSymbolAddress((void**)&wah, g_wah16); cudaGetSymbolAddress((void**)&wal, g_wal16);
    cudaGetSymbolAddress((void**)&wph, g_wph16); cudaGetSymbolAddress((void**)&wpl, g_wpl16);
    cudaGetSymbolAddress((void**)&qh,  g_qh);    cudaGetSymbolAddress((void**)&ql,  g_ql);
    cudaGetSymbolAddress((void**)&kh,  g_kh);    cudaGetSymbolAddress((void**)&kl,  g_kl);
    cudaGetSymbolAddress((void**)&vh,  g_vh);    cudaGetSymbolAddress((void**)&vl,  g_vl);
    cudaGetSymbolAddress((void**)&y16, g_y16);

    cudaFuncSetAttribute(gemm_fp16<0>, cudaFuncAttributeMaxDynamicSharedMemorySize, G_SMEM);
    cudaFuncSetAttribute(gemm_fp16<1>, cudaFuncAttributeMaxDynamicSharedMemorySize, G_SMEM);
    cudaFuncSetAttribute(flash_mma,    cudaFuncAttributeMaxDynamicSharedMemorySize, FLASH_SMEM);

    split_h <<<(M1*K1/4 + 255)/256, 256>>>(x,      (uint32_t*)x16, M1*K1/4);
    split_hl<<<(N1*K1/4 + 255)/256, 256>>>(w_attn, (uint32_t*)wah, (uint32_t*)wal, N1*K1/4);
    split_hl<<<(CC*CC/4 + 255)/256, 256>>>(w_proj, (uint32_t*)wph, (uint32_t*)wpl, CC*CC/4);

    gemm_fp16<0><<<dim3(N1/128, M1/128), 256, G_SMEM>>>(
        x16, wah, wal, K1, N1, qh, ql, kh, kl, vh, vl, nullptr, nullptr);

    flash_mma<<<dim3(TT/128, BB*HH), 256, FLASH_SMEM>>>(qh, ql, kh, kl, vh, vl, y16);

    gemm_fp16<1><<<dim3(CC/128, M1/128), 256, G_SMEM>>>(
        y16, wph, wpl, K1, CC, nullptr, nullptr, nullptr, nullptr, nullptr, nullptr,
        out, b_proj);
}

// round 6
// speedup vs baseline: 4.5993x; 1.1666x over previous
#include <cuda_runtime.h>
#include <cuda_bf16.h>
#include <cuda_fp16.h>
#include <cstdint>

#define BB 2
#define TT 2048
#define CC 2048
#define HH 16
#define HD 128
#define M1 (BB*TT)      // 4096
#define N1 (3*CC)       // 6144
#define K1 CC           // 2048

// ---------------- device scratch ----------------
__device__ __half g_x16[M1*K1];
__device__ __half g_wah16[N1*K1], g_wal16[N1*K1];
__device__ __half g_wph16[CC*CC], g_wpl16[CC*CC];
__device__ __half g_qh16[BB*HH*TT*HD], g_ql16[BB*HH*TT*HD];
__device__ __half g_k16[BB*HH*TT*HD];
__device__ __half g_v16[BB*HH*TT*HD];
__device__ __half g_y16[M1*CC];

// ---------------- helpers ----------------
__device__ __forceinline__ uint32_t smem_u32(const void* p) {
    return (uint32_t)__cvta_generic_to_shared(p);
}
__device__ __forceinline__ void ldsm_x4(uint32_t& r0, uint32_t& r1,
                                        uint32_t& r2, uint32_t& r3, uint32_t addr) {
    asm volatile("ldmatrix.sync.aligned.m8n8.x4.shared.b16 {%0,%1,%2,%3}, [%4];\n"
                 : "=r"(r0), "=r"(r1), "=r"(r2), "=r"(r3) : "r"(addr));
}
__device__ __forceinline__ void ldsm_x4t(uint32_t& r0, uint32_t& r1,
                                         uint32_t& r2, uint32_t& r3, uint32_t addr) {
    asm volatile("ldmatrix.sync.aligned.m8n8.x4.trans.shared.b16 {%0,%1,%2,%3}, [%4];\n"
                 : "=r"(r0), "=r"(r1), "=r"(r2), "=r"(r3) : "r"(addr));
}
__device__ __forceinline__ void mma_fp16(float* c,
                                         uint32_t a0, uint32_t a1, uint32_t a2, uint32_t a3,
                                         uint32_t b0, uint32_t b1) {
    asm volatile("mma.sync.aligned.m16n8k16.row.col.f32.f16.f16.f32 "
                 "{%0,%1,%2,%3}, {%4,%5,%6,%7}, {%8,%9}, {%0,%1,%2,%3};\n"
                 : "+f"(c[0]), "+f"(c[1]), "+f"(c[2]), "+f"(c[3])
                 : "r"(a0), "r"(a1), "r"(a2), "r"(a3), "r"(b0), "r"(b1));
}
__device__ __forceinline__ void split2h(float x, float y, uint32_t& hi, uint32_t& lo) {
    __half2 h = __floats2half2_rn(x, y);
    float hx = __low2float(h);
    float hy = __high2float(h);
    __half2 l = __floats2half2_rn(x - hx, y - hy);
    hi = *(uint32_t*)&h;
    lo = *(uint32_t*)&l;
}
__device__ __forceinline__ void cp16(uint32_t saddr, const void* g) {
    asm volatile("cp.async.cg.shared.global [%0], [%1], 16;\n" :: "r"(saddr), "l"(g));
}
#define CP_COMMIT() asm volatile("cp.async.commit_group;\n" ::: "memory")
#define CP_WAIT(N)  asm volatile("cp.async.wait_group %0;\n" :: "n"(N) : "memory")

// ---------------- split kernels ----------------
__global__ void split_h(const float* __restrict__ in, uint32_t* __restrict__ hi, int n4)
{
    int i = blockIdx.x * blockDim.x + threadIdx.x;
    if (i >= n4) return;
    float4 v = ((const float4*)in)[i];
    __half2 h0 = __floats2half2_rn(v.x, v.y);
    __half2 h1 = __floats2half2_rn(v.z, v.w);
    hi[i*2]   = *(uint32_t*)&h0;
    hi[i*2+1] = *(uint32_t*)&h1;
}
__global__ void split_hl(const float* __restrict__ in,
                         uint32_t* __restrict__ hi, uint32_t* __restrict__ lo, int n4)
{
    int i = blockIdx.x * blockDim.x + threadIdx.x;
    if (i >= n4) return;
    float4 v = ((const float4*)in)[i];
    uint32_t h0, l0, h1, l1;
    split2h(v.x, v.y, h0, l0);
    split2h(v.z, v.w, h1, l1);
    hi[i*2] = h0; hi[i*2+1] = h1;
    lo[i*2] = l0; lo[i*2+1] = l1;
}

// ---------------------------------------------------------------------------
// fp16 2-term GEMM: C = A(MxK) * W(NxK)^T.  A single fp16; W split hi/lo.
// 128x128x32 tile, 8 warps, cp.async double-buffered.
// EPI 0: qkv scatter (q split fp16 hi/lo with scale*log2e; k,v single fp16);
// EPI 1: fp32 out + bias.
// ---------------------------------------------------------------------------
#define GSK 40
#define GTSZ (128*GSK)
#define G_SMEM (2*3*GTSZ*2)

template<int EPI>
__global__ __launch_bounds__(256, 2)
void gemm_fp16(const __half* __restrict__ A,
               const __half* __restrict__ Wh, const __half* __restrict__ Wl,
               int Kd, int Nd,
               __half* qh, __half* ql, __half* k16, __half* v16,
               float* fout, const float* __restrict__ bias)
{
    extern __shared__ __half gs[];

    const int tid  = threadIdx.x;
    const int lane = tid & 31;
    const int wid  = tid >> 5;
    const int wm   = wid >> 2;
    const int wn   = wid & 3;
    const int m0   = blockIdx.y * 128;
    const int n0   = blockIdx.x * 128;

    float c[4][4][4];
#pragma unroll
    for (int mt = 0; mt < 4; mt++)
#pragma unroll
        for (int nt = 0; nt < 4; nt++)
#pragma unroll
            for (int r = 0; r < 4; r++) c[mt][nt][r] = 0.0f;

    const int lm_row = lane & 15;
    const int lm_kc  = (lane >> 4) << 3;

    auto issue = [&](int s, int kt) {
        __half* stg = gs + s * 3 * GTSZ;
#pragma unroll
        for (int it = 0; it < 6; it++) {
            int g   = tid + it * 256;
            int sel = g >> 9;
            int rem = g & 511;
            int row = rem >> 2;
            int col = (rem & 3) * 8;
            const __half* src = (sel == 0) ? (A  + (size_t)(m0 + row) * Kd + kt + col)
                             : ((sel == 1) ? (Wh + (size_t)(n0 + row) * Kd + kt + col)
                                           : (Wl + (size_t)(n0 + row) * Kd + kt + col));
            cp16(smem_u32(stg + sel * GTSZ + row * GSK + col), src);
        }
    };

    const int nk = Kd / 32;
    issue(0, 0);
    CP_COMMIT();

    for (int i = 0; i < nk; i++) {
        if (i + 1 < nk) {
            issue((i + 1) & 1, (i + 1) * 32);
            CP_COMMIT();
            CP_WAIT(1);
        } else {
            CP_WAIT(0);
        }
        __syncthreads();

        const __half* sA  = gs + (i & 1) * 3 * GTSZ;
        const __half* sBh = sA + GTSZ;
        const __half* sBl = sA + 2 * GTSZ;

#pragma unroll
        for (int ks = 0; ks < 32; ks += 16) {
            uint32_t bh[4][2], bl[4][2];
#pragma unroll
            for (int p = 0; p < 2; p++) {
                uint32_t r0, r1, r2, r3;
                int nrow = wn * 32 + p * 16 + lm_row;
                ldsm_x4(r0, r1, r2, r3, smem_u32(sBh + nrow*GSK + ks + lm_kc));
                bh[2*p][0] = r0; bh[2*p+1][0] = r1;
                bh[2*p][1] = r2; bh[2*p+1][1] = r3;
                ldsm_x4(r0, r1, r2, r3, smem_u32(sBl + nrow*GSK + ks + lm_kc));
                bl[2*p][0] = r0; bl[2*p+1][0] = r1;
                bl[2*p][1] = r2; bl[2*p+1][1] = r3;
            }
#pragma unroll
            for (int mt = 0; mt < 4; mt++) {
                uint32_t a0, a1, a2, a3;
                int mrow = wm * 64 + mt * 16 + lm_row;
                ldsm_x4(a0, a1, a2, a3, smem_u32(sA + mrow*GSK + ks + lm_kc));
#pragma unroll
                for (int nt = 0; nt < 4; nt++) {
                    mma_fp16(c[mt][nt], a0, a1, a2, a3, bh[nt][0], bh[nt][1]);
                    mma_fp16(c[mt][nt], a0, a1, a2, a3, bl[nt][0], bl[nt][1]);
                }
            }
        }
        __syncthreads();
    }

    // epilogue
    const int lrow = lane >> 2;
    const int lcol = (lane & 3) << 1;
    // 1/sqrt(128) * log2(e): folded so flash can use exp2
    const float qscale = 0.08838834764831845f * 1.4426950408889634f;
#pragma unroll
    for (int mt = 0; mt < 4; mt++) {
        int mbase = m0 + wm * 64 + mt * 16 + lrow;
#pragma unroll
        for (int nt = 0; nt < 4; nt++) {
            int nbase = n0 + wn * 32 + nt * 8 + lcol;
#pragma unroll
            for (int sI = 0; sI < 2; sI++) {
                int m = mbase + sI * 8;
                float v0 = c[mt][nt][sI*2 + 0];
                float v1 = c[mt][nt][sI*2 + 1];
                if (EPI == 0) {
                    int bb = m >> 11;
                    int t  = m & 2047;
                    int which = nbase >> 11;
                    int cidx  = nbase & 2047;
                    int h     = cidx >> 7;
                    int d     = cidx & 127;
                    size_t idx = (((size_t)(bb * HH + h)) * TT + t) * HD + d;
                    if (which == 0) {
                        uint32_t hi, lo;
                        split2h(v0 * qscale, v1 * qscale, hi, lo);
                        *(uint32_t*)&qh[idx] = hi;
                        *(uint32_t*)&ql[idx] = lo;
                    } else {
                        __half2 p = __floats2half2_rn(v0, v1);
                        __half* dst = (which == 1) ? k16 : v16;
                        *(uint32_t*)&dst[idx] = *(uint32_t*)&p;
                    }
                } else {
                    float2 w;
                    w.x = v0 + bias[nbase];
                    w.y = v1 + bias[nbase + 1];
                    *(float2*)&fout[(size_t)m * Nd + nbase] = w;
                }
            }
        }
    }
}

// ---------------------------------------------------------------------------
// Flash attention (mma.sync fp16), causal. BQ=128, BKV=64, 8 warps.
// S = (Qh + Ql) K^T (2-term); P,V single fp16 (1-term). exp2-domain softmax.
// ---------------------------------------------------------------------------
#define FSTR 136
#define FL_TILE (64*FSTR)
#define FL_STG  (2*FL_TILE)
#define FLASH_SMEM ((2*128*FSTR + 2*FL_STG) * 2)   // 139264 bytes

__global__ __launch_bounds__(256, 1)
void flash_mma(const __half* __restrict__ qh, const __half* __restrict__ ql,
               const __half* __restrict__ k16, const __half* __restrict__ v16,
               __half* __restrict__ y16)
{
    extern __shared__ __half fs[];
    __half* Qh   = fs;
    __half* Ql   = Qh + 128 * FSTR;
    __half* stg0 = Ql + 128 * FSTR;

    const int qt  = gridDim.x - 1 - blockIdx.x;   // heavy tiles first
    const int bh  = blockIdx.y;
    const int tid = threadIdx.x;
    const int lane = tid & 31;
    const int w    = tid >> 5;

    const size_t base = (size_t)bh * TT * HD;

#pragma unroll
    for (int it = 0; it < 8; it++) {
        int idx = tid + it * 256;
        int r   = idx >> 4;
        int c8  = (idx & 15) * 8;
        size_t g = base + (size_t)(qt * 128 + r) * HD + c8;
        *(uint4*)&Qh[r * FSTR + c8] = *(const uint4*)&qh[g];
        *(uint4*)&Ql[r * FSTR + c8] = *(const uint4*)&ql[g];
    }

    auto issue_kv = [&](int s, int jt) {
        __half* sbase = stg0 + s * FL_STG;
#pragma unroll
        for (int it = 0; it < 8; it++) {
            int g   = tid + it * 256;     // 0..2047
            int sel = g >> 10;            // 0=K, 1=V
            int rem = g & 1023;
            int row = rem >> 4;
            int c8  = (rem & 15) * 8;
            const __half* src = sel ? v16 : k16;
            cp16(smem_u32(sbase + sel * FL_TILE + row * FSTR + c8),
                 src + base + (size_t)(jt * 64 + row) * HD + c8);
        }
    };

    float m0 = -1e30f, m1 = -1e30f, l0 = 0.0f, l1 = 0.0f;
    float co[16][4];
#pragma unroll
    for (int dt = 0; dt < 16; dt++)
#pragma unroll
        for (int r = 0; r < 4; r++) co[dt][r] = 0.0f;

    const int lm_row = lane & 15;
    const int lm_kc  = (lane >> 4) << 3;
    const int row0   = qt * 128 + w * 16 + (lane >> 2);

    const int nkt = 2 * qt + 2;
    issue_kv(0, 0);
    CP_COMMIT();

    for (int jt = 0; jt < nkt; jt++) {
        if (jt + 1 < nkt) {
            issue_kv((jt + 1) & 1, jt + 1);
            CP_COMMIT();
            CP_WAIT(1);
        } else {
            CP_WAIT(0);
        }
        __syncthreads();

        const __half* Ks = stg0 + (jt & 1) * FL_STG;
        const __half* Vs = Ks + FL_TILE;

        float s[8][4];
#pragma unroll
        for (int nt = 0; nt < 8; nt++)
#pragma unroll
            for (int r = 0; r < 4; r++) s[nt][r] = 0.0f;

#pragma unroll
        for (int kc = 0; kc < 8; kc++) {
            uint32_t a0, a1, a2, a3, e0, e1, e2, e3;
            int qrow = w * 16 + lm_row;
            ldsm_x4(a0, a1, a2, a3, smem_u32(Qh + qrow*FSTR + kc*16 + lm_kc));
            ldsm_x4(e0, e1, e2, e3, smem_u32(Ql + qrow*FSTR + kc*16 + lm_kc));
#pragma unroll
            for (int p = 0; p < 4; p++) {
                uint32_t r0, r1, r2, r3;
                int krow = p * 16 + lm_row;
                ldsm_x4(r0, r1, r2, r3, smem_u32(Ks + krow*FSTR + kc*16 + lm_kc));
                mma_fp16(s[2*p],   a0, a1, a2, a3, r0, r2);
                mma_fp16(s[2*p],   e0, e1, e2, e3, r0, r2);
                mma_fp16(s[2*p+1], a0, a1, a2, a3, r1, r3);
                mma_fp16(s[2*p+1], e0, e1, e2, e3, r1, r3);
            }
        }

        if (jt * 64 + 63 > qt * 128 + w * 16) {
#pragma unroll
            for (int nt = 0; nt < 8; nt++) {
                int colb = jt * 64 + nt * 8 + (lane & 3) * 2;
#pragma unroll
                for (int e = 0; e < 2; e++) {
                    if (colb + e > row0)     s[nt][e]     = -1e30f;
                    if (colb + e > row0 + 8) s[nt][2 + e] = -1e30f;
                }
            }
        }

        float mx0 = -1e30f, mx1 = -1e30f;
#pragma unroll
        for (int nt = 0; nt < 8; nt++) {
            mx0 = fmaxf(mx0, fmaxf(s[nt][0], s[nt][1]));
            mx1 = fmaxf(mx1, fmaxf(s[nt][2], s[nt][3]));
        }
        mx0 = fmaxf(mx0, __shfl_xor_sync(0xffffffffu, mx0, 1));
        mx0 = fmaxf(mx0, __shfl_xor_sync(0xffffffffu, mx0, 2));
        mx1 = fmaxf(mx1, __shfl_xor_sync(0xffffffffu, mx1, 1));
        mx1 = fmaxf(mx1, __shfl_xor_sync(0xffffffffu, mx1, 2));

        float mn0 = fmaxf(m0, mx0);
        float mn1 = fmaxf(m1, mx1);
        float cr0 = exp2f(m0 - mn0);
        float cr1 = exp2f(m1 - mn1);
        m0 = mn0; m1 = mn1;

        float rs0 = 0.0f, rs1 = 0.0f;
#pragma unroll
        for (int nt = 0; nt < 8; nt++) {
            s[nt][0] = exp2f(s[nt][0] - mn0);
            s[nt][1] = exp2f(s[nt][1] - mn0);
            s[nt][2] = exp2f(s[nt][2] - mn1);
            s[nt][3] = exp2f(s[nt][3] - mn1);
            rs0 += s[nt][0] + s[nt][1];
            rs1 += s[nt][2] + s[nt][3];
        }
        rs0 += __shfl_xor_sync(0xffffffffu, rs0, 1);
        rs0 += __shfl_xor_sync(0xffffffffu, rs0, 2);
        rs1 += __shfl_xor_sync(0xffffffffu, rs1, 1);
        rs1 += __shfl_xor_sync(0xffffffffu, rs1, 2);
        l0 = l0 * cr0 + rs0;
        l1 = l1 * cr1 + rs1;

#pragma unroll
        for (int dt = 0; dt < 16; dt++) {
            co[dt][0] *= cr0; co[dt][1] *= cr0;
            co[dt][2] *= cr1; co[dt][3] *= cr1;
        }

        // O += P V (P,V single fp16)
#pragma unroll
        for (int kc2 = 0; kc2 < 4; kc2++) {
            __half2 hp;
            uint32_t p0, p1, p2, p3;
            hp = __floats2half2_rn(s[2*kc2][0],   s[2*kc2][1]);   p0 = *(uint32_t*)&hp;
            hp = __floats2half2_rn(s[2*kc2][2],   s[2*kc2][3]);   p1 = *(uint32_t*)&hp;
            hp = __floats2half2_rn(s[2*kc2+1][0], s[2*kc2+1][1]); p2 = *(uint32_t*)&hp;
            hp = __floats2half2_rn(s[2*kc2+1][2], s[2*kc2+1][3]); p3 = *(uint32_t*)&hp;
#pragma unroll
            for (int dp = 0; dp < 8; dp++) {
                uint32_t v0, v1, v2, v3;
                int vrow = kc2 * 16 + lm_row;
                ldsm_x4t(v0, v1, v2, v3, smem_u32(Vs + vrow*FSTR + dp*16 + lm_kc));
                mma_fp16(co[2*dp],   p0, p1, p2, p3, v0, v1);
                mma_fp16(co[2*dp+1], p0, p1, p2, p3, v2, v3);
            }
        }
        __syncthreads();
    }

    const float inv0 = 1.0f / l0;
    const float inv1 = 1.0f / l1;
    const int b = bh >> 4;
    const int h = bh & 15;
#pragma unroll
    for (int dt = 0; dt < 16; dt++) {
        int d = dt * 8 + (lane & 3) * 2;
        size_t i0 = ((size_t)(b * TT + row0)) * CC + h * HD + d;
        __half2 p0 = __floats2half2_rn(co[dt][0] * inv0, co[dt][1] * inv0);
        *(uint32_t*)&y16[i0] = *(uint32_t*)&p0;
        size_t i1 = ((size_t)(b * TT + row0 + 8)) * CC + h * HD + d;
        __half2 p1 = __floats2half2_rn(co[dt][2] * inv1, co[dt][3] * inv1);
        *(uint32_t*)&y16[i1] = *(uint32_t*)&p1;
    }
}

// ---------------------------------------------------------------------------
extern "C" void kernel_launch(void* const* d_in, const int* in_sizes, int n_in,
                              void* d_out, int out_size)
{
    const float* x      = (const float*)d_in[0];
    const float* w_attn = (const float*)d_in[1];
    const float* w_proj = (const float*)d_in[2];
    const float* b_proj = (const float*)d_in[3];
    float* out = (float*)d_out;

    __half *x16, *wah, *wal, *wph, *wpl, *y16;
    __half *qh, *ql, *k16, *v16;
    cudaGetSymbolAddress((void**)&x16, g_x16);
    cudaGetSymbolAddress((void**)&wah, g_wah16); cudaGetSymbolAddress((void**)&wal, g_wal16);
    cudaGetSymbolAddress((void**)&wph, g_wph16); cudaGetSymbolAddress((void**)&wpl, g_wpl16);
    cudaGetSymbolAddress((void**)&qh,  g_qh16);  cudaGetSymbolAddress((void**)&ql,  g_ql16);
    cudaGetSymbolAddress((void**)&k16, g_k16);   cudaGetSymbolAddress((void**)&v16, g_v16);
    cudaGetSymbolAddress((void**)&y16, g_y16);

    cudaFuncSetAttribute(gemm_fp16<0>, cudaFuncAttributeMaxDynamicSharedMemorySize, G_SMEM);
    cudaFuncSetAttribute(gemm_fp16<1>, cudaFuncAttributeMaxDynamicSharedMemorySize, G_SMEM);
    cudaFuncSetAttribute(flash_mma,    cudaFuncAttributeMaxDynamicSharedMemorySize, FLASH_SMEM);

    split_h <<<(M1*K1/4 + 255)/256, 256>>>(x,      (uint32_t*)x16, M1*K1/4);
    split_hl<<<(N1*K1/4 + 255)/256, 256>>>(w_attn, (uint32_t*)wah, (uint32_t*)wal, N1*K1/4);
    split_hl<<<(CC*CC/4 + 255)/256, 256>>>(w_proj, (uint32_t*)wph, (uint32_t*)wpl, CC*CC/4);

    gemm_fp16<0><<<dim3(N1/128, M1/128), 256, G_SMEM>>>(
        x16, wah, wal, K1, N1, qh, ql, k16, v16, nullptr, nullptr);

    flash_mma<<<dim3(TT/128, BB*HH), 256, FLASH_SMEM>>>(qh, ql, k16, v16, y16);

    gemm_fp16<1><<<dim3(CC/128, M1/128), 256, G_SMEM>>>(
        y16, wph, wpl, K1, CC, nullptr, nullptr, nullptr, nullptr,
        out, b_proj);
}

// round 7
// speedup vs baseline: 6.5227x; 1.4182x over previous
#include <cuda_runtime.h>
#include <cuda_bf16.h>
#include <cuda_fp16.h>
#include <cstdint>

#define BB 2
#define TT 2048
#define CC 2048
#define HH 16
#define HD 128
#define M1 (BB*TT)      // 4096
#define N1 (3*CC)       // 6144
#define K1 CC           // 2048

// ---------------- device scratch ----------------
__device__ __half g_x16[M1*K1];
__device__ __half g_wa16[N1*K1];
__device__ __half g_wp16[CC*CC];
__device__ __half g_qh16[BB*HH*TT*HD], g_ql16[BB*HH*TT*HD];
__device__ __half g_k16[BB*HH*TT*HD];
__device__ __half g_v16[BB*HH*TT*HD];
__device__ __half g_y16[M1*CC];

// ---------------- helpers ----------------
__device__ __forceinline__ uint32_t smem_u32(const void* p) {
    return (uint32_t)__cvta_generic_to_shared(p);
}
__device__ __forceinline__ void ldsm_x4(uint32_t& r0, uint32_t& r1,
                                        uint32_t& r2, uint32_t& r3, uint32_t addr) {
    asm volatile("ldmatrix.sync.aligned.m8n8.x4.shared.b16 {%0,%1,%2,%3}, [%4];\n"
                 : "=r"(r0), "=r"(r1), "=r"(r2), "=r"(r3) : "r"(addr));
}
__device__ __forceinline__ void ldsm_x4t(uint32_t& r0, uint32_t& r1,
                                         uint32_t& r2, uint32_t& r3, uint32_t addr) {
    asm volatile("ldmatrix.sync.aligned.m8n8.x4.trans.shared.b16 {%0,%1,%2,%3}, [%4];\n"
                 : "=r"(r0), "=r"(r1), "=r"(r2), "=r"(r3) : "r"(addr));
}
__device__ __forceinline__ void mma_fp16(float* c,
                                         uint32_t a0, uint32_t a1, uint32_t a2, uint32_t a3,
                                         uint32_t b0, uint32_t b1) {
    asm volatile("mma.sync.aligned.m16n8k16.row.col.f32.f16.f16.f32 "
                 "{%0,%1,%2,%3}, {%4,%5,%6,%7}, {%8,%9}, {%0,%1,%2,%3};\n"
                 : "+f"(c[0]), "+f"(c[1]), "+f"(c[2]), "+f"(c[3])
                 : "r"(a0), "r"(a1), "r"(a2), "r"(a3), "r"(b0), "r"(b1));
}
__device__ __forceinline__ void split2h(float x, float y, uint32_t& hi, uint32_t& lo) {
    __half2 h = __floats2half2_rn(x, y);
    float hx = __low2float(h);
    float hy = __high2float(h);
    __half2 l = __floats2half2_rn(x - hx, y - hy);
    hi = *(uint32_t*)&h;
    lo = *(uint32_t*)&l;
}
__device__ __forceinline__ void cp16(uint32_t saddr, const void* g) {
    asm volatile("cp.async.cg.shared.global [%0], [%1], 16;\n" :: "r"(saddr), "l"(g));
}
#define CP_COMMIT() asm volatile("cp.async.commit_group;\n" ::: "memory")
#define CP_WAIT(N)  asm volatile("cp.async.wait_group %0;\n" :: "n"(N) : "memory")

// ---------------- fp32 -> fp16 cast kernel ----------------
__global__ void split_h(const float* __restrict__ in, uint32_t* __restrict__ hi, int n4)
{
    int i = blockIdx.x * blockDim.x + threadIdx.x;
    if (i >= n4) return;
    float4 v = ((const float4*)in)[i];
    __half2 h0 = __floats2half2_rn(v.x, v.y);
    __half2 h1 = __floats2half2_rn(v.z, v.w);
    hi[i*2]   = *(uint32_t*)&h0;
    hi[i*2+1] = *(uint32_t*)&h1;
}

// ---------------------------------------------------------------------------
// 1-term fp16 GEMM: C = A(MxK) * W(NxK)^T, fp32 accumulate.
// 128x128x32 tile, 8 warps (2x4), warp tile 64x32, cp.async double-buffered.
// EPI 0: qkv scatter (q split fp16 hi/lo with scale*log2e; k,v single fp16);
// EPI 1: fp32 out + bias.
// ---------------------------------------------------------------------------
#define GSK 40
#define GTSZ (128*GSK)
#define G_SMEM (2*2*GTSZ*2)   // 2 stages * 2 tiles * 5120 halves

template<int EPI>
__global__ __launch_bounds__(256, 2)
void gemm_fp16(const __half* __restrict__ A, const __half* __restrict__ W,
               int Kd, int Nd,
               __half* qh, __half* ql, __half* k16, __half* v16,
               float* fout, const float* __restrict__ bias)
{
    extern __shared__ __half gs[];

    const int tid  = threadIdx.x;
    const int lane = tid & 31;
    const int wid  = tid >> 5;
    const int wm   = wid >> 2;
    const int wn   = wid & 3;
    const int m0   = blockIdx.y * 128;
    const int n0   = blockIdx.x * 128;

    float c[4][4][4];
#pragma unroll
    for (int mt = 0; mt < 4; mt++)
#pragma unroll
        for (int nt = 0; nt < 4; nt++)
#pragma unroll
            for (int r = 0; r < 4; r++) c[mt][nt][r] = 0.0f;

    const int lm_row = lane & 15;
    const int lm_kc  = (lane >> 4) << 3;

    auto issue = [&](int s, int kt) {
        __half* stg = gs + s * 2 * GTSZ;
#pragma unroll
        for (int it = 0; it < 4; it++) {
            int g   = tid + it * 256;       // 0..1023
            int sel = g >> 9;               // 0=A, 1=W
            int rem = g & 511;
            int row = rem >> 2;
            int col = (rem & 3) * 8;
            const __half* src = (sel == 0) ? (A + (size_t)(m0 + row) * Kd + kt + col)
                                           : (W + (size_t)(n0 + row) * Kd + kt + col);
            cp16(smem_u32(stg + sel * GTSZ + row * GSK + col), src);
        }
    };

    const int nk = Kd / 32;
    issue(0, 0);
    CP_COMMIT();

    for (int i = 0; i < nk; i++) {
        if (i + 1 < nk) {
            issue((i + 1) & 1, (i + 1) * 32);
            CP_COMMIT();
            CP_WAIT(1);
        } else {
            CP_WAIT(0);
        }
        __syncthreads();

        const __half* sA = gs + (i & 1) * 2 * GTSZ;
        const __half* sB = sA + GTSZ;

#pragma unroll
        for (int ks = 0; ks < 32; ks += 16) {
            uint32_t bh[4][2];
#pragma unroll
            for (int p = 0; p < 2; p++) {
                uint32_t r0, r1, r2, r3;
                int nrow = wn * 32 + p * 16 + lm_row;
                ldsm_x4(r0, r1, r2, r3, smem_u32(sB + nrow*GSK + ks + lm_kc));
                bh[2*p][0] = r0; bh[2*p+1][0] = r1;
                bh[2*p][1] = r2; bh[2*p+1][1] = r3;
            }
#pragma unroll
            for (int mt = 0; mt < 4; mt++) {
                uint32_t a0, a1, a2, a3;
                int mrow = wm * 64 + mt * 16 + lm_row;
                ldsm_x4(a0, a1, a2, a3, smem_u32(sA + mrow*GSK + ks + lm_kc));
#pragma unroll
                for (int nt = 0; nt < 4; nt++)
                    mma_fp16(c[mt][nt], a0, a1, a2, a3, bh[nt][0], bh[nt][1]);
            }
        }
        __syncthreads();
    }

    // epilogue
    const int lrow = lane >> 2;
    const int lcol = (lane & 3) << 1;
    // 1/sqrt(128) * log2(e): folded so flash can use exp2
    const float qscale = 0.08838834764831845f * 1.4426950408889634f;
#pragma unroll
    for (int mt = 0; mt < 4; mt++) {
        int mbase = m0 + wm * 64 + mt * 16 + lrow;
#pragma unroll
        for (int nt = 0; nt < 4; nt++) {
            int nbase = n0 + wn * 32 + nt * 8 + lcol;
#pragma unroll
            for (int sI = 0; sI < 2; sI++) {
                int m = mbase + sI * 8;
                float v0 = c[mt][nt][sI*2 + 0];
                float v1 = c[mt][nt][sI*2 + 1];
                if (EPI == 0) {
                    int bb = m >> 11;
                    int t  = m & 2047;
                    int which = nbase >> 11;
                    int cidx  = nbase & 2047;
                    int h     = cidx >> 7;
                    int d     = cidx & 127;
                    size_t idx = (((size_t)(bb * HH + h)) * TT + t) * HD + d;
                    if (which == 0) {
                        uint32_t hi, lo;
                        split2h(v0 * qscale, v1 * qscale, hi, lo);
                        *(uint32_t*)&qh[idx] = hi;
                        *(uint32_t*)&ql[idx] = lo;
                    } else {
                        __half2 p = __floats2half2_rn(v0, v1);
                        __half* dst = (which == 1) ? k16 : v16;
                        *(uint32_t*)&dst[idx] = *(uint32_t*)&p;
                    }
                } else {
                    float2 w;
                    w.x = v0 + bias[nbase];
                    w.y = v1 + bias[nbase + 1];
                    *(float2*)&fout[(size_t)m * Nd + nbase] = w;
                }
            }
        }
    }
}

// ---------------------------------------------------------------------------
// Flash attention (mma.sync fp16), causal. BQ=128, BKV=64, 8 warps.
// S = (Qh + Ql) K^T (2-term); P,V single fp16 (1-term). exp2-domain softmax.
// ---------------------------------------------------------------------------
#define FSTR 136
#define FL_TILE (64*FSTR)
#define FL_STG  (2*FL_TILE)
#define FLASH_SMEM ((2*128*FSTR + 2*FL_STG) * 2)   // 139264 bytes

__global__ __launch_bounds__(256, 1)
void flash_mma(const __half* __restrict__ qh, const __half* __restrict__ ql,
               const __half* __restrict__ k16, const __half* __restrict__ v16,
               __half* __restrict__ y16)
{
    extern __shared__ __half fs[];
    __half* Qh   = fs;
    __half* Ql   = Qh + 128 * FSTR;
    __half* stg0 = Ql + 128 * FSTR;

    const int qt  = gridDim.x - 1 - blockIdx.x;   // heavy tiles first
    const int bh  = blockIdx.y;
    const int tid = threadIdx.x;
    const int lane = tid & 31;
    const int w    = tid >> 5;

    const size_t base = (size_t)bh * TT * HD;

#pragma unroll
    for (int it = 0; it < 8; it++) {
        int idx = tid + it * 256;
        int r   = idx >> 4;
        int c8  = (idx & 15) * 8;
        size_t g = base + (size_t)(qt * 128 + r) * HD + c8;
        *(uint4*)&Qh[r * FSTR + c8] = *(const uint4*)&qh[g];
        *(uint4*)&Ql[r * FSTR + c8] = *(const uint4*)&ql[g];
    }

    auto issue_kv = [&](int s, int jt) {
        __half* sbase = stg0 + s * FL_STG;
#pragma unroll
        for (int it = 0; it < 8; it++) {
            int g   = tid + it * 256;     // 0..2047
            int sel = g >> 10;            // 0=K, 1=V
            int rem = g & 1023;
            int row = rem >> 4;
            int c8  = (rem & 15) * 8;
            const __half* src = sel ? v16 : k16;
            cp16(smem_u32(sbase + sel * FL_TILE + row * FSTR + c8),
                 src + base + (size_t)(jt * 64 + row) * HD + c8);
        }
    };

    float m0 = -1e30f, m1 = -1e30f, l0 = 0.0f, l1 = 0.0f;
    float co[16][4];
#pragma unroll
    for (int dt = 0; dt < 16; dt++)
#pragma unroll
        for (int r = 0; r < 4; r++) co[dt][r] = 0.0f;

    const int lm_row = lane & 15;
    const int lm_kc  = (lane >> 4) << 3;
    const int row0   = qt * 128 + w * 16 + (lane >> 2);

    const int nkt = 2 * qt + 2;
    issue_kv(0, 0);
    CP_COMMIT();

    for (int jt = 0; jt < nkt; jt++) {
        if (jt + 1 < nkt) {
            issue_kv((jt + 1) & 1, jt + 1);
            CP_COMMIT();
            CP_WAIT(1);
        } else {
            CP_WAIT(0);
        }
        __syncthreads();

        const __half* Ks = stg0 + (jt & 1) * FL_STG;
        const __half* Vs = Ks + FL_TILE;

        float s[8][4];
#pragma unroll
        for (int nt = 0; nt < 8; nt++)
#pragma unroll
            for (int r = 0; r < 4; r++) s[nt][r] = 0.0f;

#pragma unroll
        for (int kc = 0; kc < 8; kc++) {
            uint32_t a0, a1, a2, a3, e0, e1, e2, e3;
            int qrow = w * 16 + lm_row;
            ldsm_x4(a0, a1, a2, a3, smem_u32(Qh + qrow*FSTR + kc*16 + lm_kc));
            ldsm_x4(e0, e1, e2, e3, smem_u32(Ql + qrow*FSTR + kc*16 + lm_kc));
#pragma unroll
            for (int p = 0; p < 4; p++) {
                uint32_t r0, r1, r2, r3;
                int krow = p * 16 + lm_row;
                ldsm_x4(r0, r1, r2, r3, smem_u32(Ks + krow*FSTR + kc*16 + lm_kc));
                mma_fp16(s[2*p],   a0, a1, a2, a3, r0, r2);
                mma_fp16(s[2*p],   e0, e1, e2, e3, r0, r2);
                mma_fp16(s[2*p+1], a0, a1, a2, a3, r1, r3);
                mma_fp16(s[2*p+1], e0, e1, e2, e3, r1, r3);
            }
        }

        if (jt * 64 + 63 > qt * 128 + w * 16) {
#pragma unroll
            for (int nt = 0; nt < 8; nt++) {
                int colb = jt * 64 + nt * 8 + (lane & 3) * 2;
#pragma unroll
                for (int e = 0; e < 2; e++) {
                    if (colb + e > row0)     s[nt][e]     = -1e30f;
                    if (colb + e > row0 + 8) s[nt][2 + e] = -1e30f;
                }
            }
        }

        float mx0 = -1e30f, mx1 = -1e30f;
#pragma unroll
        for (int nt = 0; nt < 8; nt++) {
            mx0 = fmaxf(mx0, fmaxf(s[nt][0], s[nt][1]));
            mx1 = fmaxf(mx1, fmaxf(s[nt][2], s[nt][3]));
        }
        mx0 = fmaxf(mx0, __shfl_xor_sync(0xffffffffu, mx0, 1));
        mx0 = fmaxf(mx0, __shfl_xor_sync(0xffffffffu, mx0, 2));
        mx1 = fmaxf(mx1, __shfl_xor_sync(0xffffffffu, mx1, 1));
        mx1 = fmaxf(mx1, __shfl_xor_sync(0xffffffffu, mx1, 2));

        float mn0 = fmaxf(m0, mx0);
        float mn1 = fmaxf(m1, mx1);
        float cr0 = exp2f(m0 - mn0);
        float cr1 = exp2f(m1 - mn1);
        m0 = mn0; m1 = mn1;

        float rs0 = 0.0f, rs1 = 0.0f;
#pragma unroll
        for (int nt = 0; nt < 8; nt++) {
            s[nt][0] = exp2f(s[nt][0] - mn0);
            s[nt][1] = exp2f(s[nt][1] - mn0);
            s[nt][2] = exp2f(s[nt][2] - mn1);
            s[nt][3] = exp2f(s[nt][3] - mn1);
            rs0 += s[nt][0] + s[nt][1];
            rs1 += s[nt][2] + s[nt][3];
        }
        rs0 += __shfl_xor_sync(0xffffffffu, rs0, 1);
        rs0 += __shfl_xor_sync(0xffffffffu, rs0, 2);
        rs1 += __shfl_xor_sync(0xffffffffu, rs1, 1);
        rs1 += __shfl_xor_sync(0xffffffffu, rs1, 2);
        l0 = l0 * cr0 + rs0;
        l1 = l1 * cr1 + rs1;

#pragma unroll
        for (int dt = 0; dt < 16; dt++) {
            co[dt][0] *= cr0; co[dt][1] *= cr0;
            co[dt][2] *= cr1; co[dt][3] *= cr1;
        }

        // O += P V (P,V single fp16)
#pragma unroll
        for (int kc2 = 0; kc2 < 4; kc2++) {
            __half2 hp;
            uint32_t p0, p1, p2, p3;
            hp = __floats2half2_rn(s[2*kc2][0],   s[2*kc2][1]);   p0 = *(uint32_t*)&hp;
            hp = __floats2half2_rn(s[2*kc2][2],   s[2*kc2][3]);   p1 = *(uint32_t*)&hp;
            hp = __floats2half2_rn(s[2*kc2+1][0], s[2*kc2+1][1]); p2 = *(uint32_t*)&hp;
            hp = __floats2half2_rn(s[2*kc2+1][2], s[2*kc2+1][3]); p3 = *(uint32_t*)&hp;
#pragma unroll
            for (int dp = 0; dp < 8; dp++) {
                uint32_t v0, v1, v2, v3;
                int vrow = kc2 * 16 + lm_row;
                ldsm_x4t(v0, v1, v2, v3, smem_u32(Vs + vrow*FSTR + dp*16 + lm_kc));
                mma_fp16(co[2*dp],   p0, p1, p2, p3, v0, v1);
                mma_fp16(co[2*dp+1], p0, p1, p2, p3, v2, v3);
            }
        }
        __syncthreads();
    }

    const float inv0 = 1.0f / l0;
    const float inv1 = 1.0f / l1;
    const int b = bh >> 4;
    const int h = bh & 15;
#pragma unroll
    for (int dt = 0; dt < 16; dt++) {
        int d = dt * 8 + (lane & 3) * 2;
        size_t i0 = ((size_t)(b * TT + row0)) * CC + h * HD + d;
        __half2 p0 = __floats2half2_rn(co[dt][0] * inv0, co[dt][1] * inv0);
        *(uint32_t*)&y16[i0] = *(uint32_t*)&p0;
        size_t i1 = ((size_t)(b * TT + row0 + 8)) * CC + h * HD + d;
        __half2 p1 = __floats2half2_rn(co[dt][2] * inv1, co[dt][3] * inv1);
        *(uint32_t*)&y16[i1] = *(uint32_t*)&p1;
    }
}

// ---------------------------------------------------------------------------
extern "C" void kernel_launch(void* const* d_in, const int* in_sizes, int n_in,
                              void* d_out, int out_size)
{
    const float* x      = (const float*)d_in[0];
    const float* w_attn = (const float*)d_in[1];
    const float* w_proj = (const float*)d_in[2];
    const float* b_proj = (const float*)d_in[3];
    float* out = (float*)d_out;

    __half *x16, *wa16, *wp16, *y16;
    __half *qh, *ql, *k16, *v16;
    cudaGetSymbolAddress((void**)&x16,  g_x16);
    cudaGetSymbolAddress((void**)&wa16, g_wa16);
    cudaGetSymbolAddress((void**)&wp16, g_wp16);
    cudaGetSymbolAddress((void**)&qh,   g_qh16);
    cudaGetSymbolAddress((void**)&ql,   g_ql16);
    cudaGetSymbolAddress((void**)&k16,  g_k16);
    cudaGetSymbolAddress((void**)&v16,  g_v16);
    cudaGetSymbolAddress((void**)&y16,  g_y16);

    cudaFuncSetAttribute(gemm_fp16<0>, cudaFuncAttributeMaxDynamicSharedMemorySize, G_SMEM);
    cudaFuncSetAttribute(gemm_fp16<1>, cudaFuncAttributeMaxDynamicSharedMemorySize, G_SMEM);
    cudaFuncSetAttribute(flash_mma,    cudaFuncAttributeMaxDynamicSharedMemorySize, FLASH_SMEM);

    split_h<<<(M1*K1/4 + 255)/256, 256>>>(x,      (uint32_t*)x16,  M1*K1/4);
    split_h<<<(N1*K1/4 + 255)/256, 256>>>(w_attn, (uint32_t*)wa16, N1*K1/4);
    split_h<<<(CC*CC/4 + 255)/256, 256>>>(w_proj, (uint32_t*)wp16, CC*CC/4);

    gemm_fp16<0><<<dim3(N1/128, M1/128), 256, G_SMEM>>>(
        x16, wa16, K1, N1, qh, ql, k16, v16, nullptr, nullptr);

    flash_mma<<<dim3(TT/128, BB*HH), 256, FLASH_SMEM>>>(qh, ql, k16, v16, y16);

    gemm_fp16<1><<<dim3(CC/128, M1/128), 256, G_SMEM>>>(
        y16, wp16, K1, CC, nullptr, nullptr, nullptr, nullptr,
        out, b_proj);
}